// round 10
// baseline (speedup 1.0000x reference)
#include <cuda_runtime.h>
#include <cuda_fp16.h>
#include <cstdint>

#define S_TOK 16384
#define D_DIM 4096
#define N_EXP 64
#define CAP   320
#define KC    64
#define NCHUNK 64
#define BM    128

#define SWZ(o) ((o) ^ (((o) >> 3) & 0x70))

// ---------------- scratch ----------------
__device__ float g_logits[S_TOK * N_EXP];
// W fp16 plane: [chunk][expert][36 words]; rows padded 128B->144B (bank spread)
__device__ __align__(16) uint32_t g_whT[NCHUNK * 2304];
__device__ int   g_e1[S_TOK];
__device__ int   g_e2[S_TOK];
__device__ int   g_want2[S_TOK];
__device__ float g_g1n[S_TOK];
__device__ float g_g2n[S_TOK];
__device__ int   g_bc1T[64 * 64];    // [expert][block]
__device__ int   g_bc2T[64 * 64];
__device__ int   g_base1T[64 * 64];
__device__ int   g_base2T[64 * 64];
__device__ int   g_cap2[64];
__device__ int   g_nflag;
__device__ int   g_flagged[S_TOK];

// ---------------- PTX helpers ----------------
__device__ __forceinline__ uint32_t smem_to_u32(const void* p) {
    uint32_t a;
    asm("{ .reg .u64 t; cvta.to.shared.u64 t, %1; cvt.u32.u64 %0, t; }" : "=r"(a) : "l"(p));
    return a;
}
#define CP_ASYNC16(dst, src) \
    asm volatile("cp.async.cg.shared.global [%0], [%1], 16;" :: "r"(dst), "l"(src) : "memory")
#define CP_ASYNC_COMMIT()  asm volatile("cp.async.commit_group;" ::: "memory")
#define CP_ASYNC_WAIT0()   asm volatile("cp.async.wait_group 0;" ::: "memory")

#define LDSM_X4(r0, r1, r2, r3, addr) \
    asm volatile("ldmatrix.sync.aligned.m8n8.x4.shared.b16 {%0,%1,%2,%3}, [%4];" \
        : "=r"(r0), "=r"(r1), "=r"(r2), "=r"(r3) : "r"(addr))

#define LDS32(r, addr) \
    asm volatile("ld.shared.b32 %0, [%1];" : "=r"(r) : "r"(addr))

#define MMA_FP16(d, a, b0, b1) \
    asm volatile("mma.sync.aligned.m16n8k16.row.col.f32.f16.f16.f32 " \
        "{%0,%1,%2,%3}, {%4,%5,%6,%7}, {%8,%9}, {%0,%1,%2,%3};" \
        : "+f"((d)[0]), "+f"((d)[1]), "+f"((d)[2]), "+f"((d)[3]) \
        : "r"((a)[0]), "r"((a)[1]), "r"((a)[2]), "r"((a)[3]), "r"(b0), "r"(b1))

// gemm smem layout
#define XS(s)  (sb + (s) * 16384)
#define WHS(s) (sb + 32768 + (s) * 9216)
#define GEMM_SMEM 51200

// ---------------- W pre-conversion (also resets flag counter) ----------------
__global__ __launch_bounds__(256)
void wconv_kernel(const float* __restrict__ W) {
    const int pid = blockIdx.x * 256 + threadIdx.x;   // 0..131071
    if (pid == 0) g_nflag = 0;
    const int n = pid >> 11;                          // expert 0..63
    const int j = pid & 2047;                         // k-pair 0..2047
    const float2 v = *(const float2*)(W + (size_t)n * D_DIM + j * 2);
    const __half h0 = __float2half_rn(v.x);
    const __half h1 = __float2half_rn(v.y);
    const uint32_t hp = (uint32_t)__half_as_ushort(h0) | ((uint32_t)__half_as_ushort(h1) << 16);
    g_whT[(j >> 5) * 2304 + n * 36 + (j & 31)] = hp;
}

// ---------------- HMMA GEMM: single fp16 product ----------------
__global__ __launch_bounds__(512, 1)
void gemm_mma(const float* __restrict__ X) {
    extern __shared__ __align__(1024) char smem[];
    const uint32_t sb = smem_to_u32(smem);
    const int tid = threadIdx.x, wid = tid >> 5, lane = tid & 31;
    const int m0 = blockIdx.x * BM;
    const int warp_m = wid & 3, warp_n = wid >> 2;   // 4M x 4N, warp tile m32 x n16

    float acc[2][2][4];
#pragma unroll
    for (int a = 0; a < 2; ++a)
#pragma unroll
        for (int b = 0; b < 2; ++b)
#pragma unroll
            for (int q = 0; q < 4; ++q) acc[a][b][q] = 0.f;

    const int xrow = tid >> 2, xc4 = tid & 3;
    const float4* xp = (const float4*)(X + (size_t)(m0 + xrow) * D_DIM);

    const uint32_t a_b0  = (uint32_t)((warp_m * 32 + (lane & 15)) * 128 + (lane >> 4) * 16);
    const uint32_t b_off = (uint32_t)((warp_n * 16 + (lane >> 2)) * 144 + (lane & 3) * 4);

    auto loadB = [&](int c, int s) {
        const char* gh = (const char*)(g_whT + c * 2304);
        const uint32_t wh = WHS(s);
        CP_ASYNC16(wh + tid * 16, gh + tid * 16);
        if (tid < 64) CP_ASYNC16(wh + (512 + tid) * 16, gh + (512 + tid) * 16);
    };
    auto loadx = [&](int c, float4* v) {
#pragma unroll
        for (int it = 0; it < 4; ++it)
            v[it] = xp[c * 16 + xc4 + it * 4];
    };
    auto storeXS = [&](int s, const float4* v) {
        const uint32_t xs = XS(s);
#pragma unroll
        for (int it = 0; it < 4; ++it) {
            const __half2 h01 = __floats2half2_rn(v[it].x, v[it].y);
            const __half2 h23 = __floats2half2_rn(v[it].z, v[it].w);
            const uint32_t p0 = *(const uint32_t*)&h01;
            const uint32_t p1 = *(const uint32_t*)&h23;
            const uint32_t off = SWZ((uint32_t)(xrow * 128 + (xc4 + it * 4) * 8));
            asm volatile("st.shared.v2.b32 [%0], {%1,%2};" :: "r"(xs + off), "r"(p0), "r"(p1) : "memory");
        }
    };

    // prologue
    float4 v[4];
    loadB(0, 0);
    CP_ASYNC_COMMIT();
    loadx(0, v);
    storeXS(0, v);
    CP_ASYNC_WAIT0();
    __syncthreads();

    for (int c = 0; c < NCHUNK; ++c) {
        const int s = c & 1;
        float4 nv[4];
        if (c + 1 < NCHUNK) {
            loadB(c + 1, s ^ 1);
            CP_ASYNC_COMMIT();
            loadx(c + 1, nv);
        }
        const uint32_t xs = XS(s), wh = WHS(s);
#pragma unroll
        for (int ks = 0; ks < 4; ++ks) {
            uint32_t ah[2][4];
            LDSM_X4(ah[0][0], ah[0][1], ah[0][2], ah[0][3], xs + SWZ(a_b0 + ks * 32));
            LDSM_X4(ah[1][0], ah[1][1], ah[1][2], ah[1][3], xs + SWZ(a_b0 + 2048 + ks * 32));
            uint32_t bh[2][2];
#pragma unroll
            for (int nt = 0; nt < 2; ++nt) {
                const uint32_t bo = b_off + nt * 1152 + ks * 32;
                LDS32(bh[nt][0], wh + bo);
                LDS32(bh[nt][1], wh + bo + 16);
            }
#pragma unroll
            for (int mt = 0; mt < 2; ++mt)
#pragma unroll
                for (int nt = 0; nt < 2; ++nt)
                    MMA_FP16(acc[mt][nt], ah[mt], bh[nt][0], bh[nt][1]);
        }
        if (c + 1 < NCHUNK) storeXS(s ^ 1, nv);
        CP_ASYNC_WAIT0();
        __syncthreads();
    }

    const int r0 = m0 + warp_m * 32 + (lane >> 2);
    const int c0 = warp_n * 16 + (lane & 3) * 2;
#pragma unroll
    for (int mt = 0; mt < 2; ++mt)
#pragma unroll
        for (int nt = 0; nt < 2; ++nt) {
            const int r = r0 + mt * 16, cc = c0 + nt * 8;
            *(float2*)&g_logits[(size_t)r * 64 + cc]       = make_float2(acc[mt][nt][0], acc[mt][nt][1]);
            *(float2*)&g_logits[(size_t)(r + 8) * 64 + cc] = make_float2(acc[mt][nt][2], acc[mt][nt][3]);
        }
}

// ---------------- Threefry-2x32 (JAX partitionable, key(1)) ----------------
__device__ __forceinline__ void threefry2x32(uint32_t x0, uint32_t x1,
                                             uint32_t& o0, uint32_t& o1) {
    const uint32_t k0 = 0u, k1 = 1u, k2 = 0x1BD11BDBu;
    x0 += k0; x1 += k1;
#define TFR(r) { x0 += x1; x1 = (x1 << (r)) | (x1 >> (32 - (r))); x1 ^= x0; }
    TFR(13) TFR(15) TFR(26) TFR(6)  x0 += k1; x1 += k2 + 1u;
    TFR(17) TFR(29) TFR(16) TFR(24) x0 += k2; x1 += k0 + 2u;
    TFR(13) TFR(15) TFR(26) TFR(6)  x0 += k0; x1 += k1 + 3u;
    TFR(17) TFR(29) TFR(16) TFR(24) x0 += k1; x1 += k2 + 4u;
    TFR(13) TFR(15) TFR(26) TFR(6)  x0 += k2; x1 += k0 + 5u;
#undef TFR
    o0 = x0; o1 = x1;
}
__device__ __forceinline__ float jax_uniform_partitionable(uint32_t i) {
    uint32_t o0, o1;
    threefry2x32(0u, i, o0, o1);
    const uint32_t bits = o0 ^ o1;
    return __uint_as_float((bits >> 9) | 0x3f800000u) - 1.0f;
}

// ---------------- fused topk + softmax + want2 + flags + block histogram ----------------
__global__ __launch_bounds__(256)
void topk256() {
    __shared__ int c1[64], c2[64];
    const int t = threadIdx.x, blk = blockIdx.x;
    const int i = blk * 256 + t;
    if (t < 64) { c1[t] = 0; c2[t] = 0; }
    __syncthreads();

    float4 L[16];
    const float4* lp = (const float4*)(g_logits + (size_t)i * 64);
#pragma unroll
    for (int q = 0; q < 16; ++q) L[q] = lp[q];

    float v1 = -3.4e38f, v2 = -3.4e38f, v3 = -3.4e38f;
    int i1 = 0, i2 = 0;
#pragma unroll
    for (int q = 0; q < 16; ++q) {
        const float e[4] = {L[q].x, L[q].y, L[q].z, L[q].w};
#pragma unroll
        for (int r = 0; r < 4; ++r) {
            const float x = e[r]; const int idx = q * 4 + r;
            if (x > v1)      { v3 = v2; v2 = v1; i2 = i1; v1 = x; i1 = idx; }
            else if (x > v2) { v3 = v2; v2 = x; i2 = idx; }
            else if (x > v3) { v3 = x; }
        }
    }
    float s = 0.f;
#pragma unroll
    for (int q = 0; q < 16; ++q)
        s += expf(L[q].x - v1) + expf(L[q].y - v1) + expf(L[q].z - v1) + expf(L[q].w - v1);

    const float g1 = 1.0f / s;
    const float g2 = expf(v2 - v1) / s;
    const float denom = g1 + g2;
    const float g1n = g1 / denom, g2n = g2 / denom;
    const float rnd = jax_uniform_partitionable((uint32_t)i);
    const int want2 = (rnd < 2.0f * g2n) ? 1 : 0;

    g_e1[i] = i1; g_e2[i] = i2;
    g_g1n[i] = g1n; g_g2n[i] = g2n;
    g_want2[i] = want2;

    const float TAU_GAP = 2e-3f, TAU_RND = 1.2e-3f;
    if ((v1 - v2) < TAU_GAP || (v2 - v3) < TAU_GAP || fabsf(rnd - 2.0f * g2n) < TAU_RND) {
        const int k = atomicAdd(&g_nflag, 1);
        g_flagged[k] = i;
    }
    atomicAdd(&c1[i1], 1);
    if (want2) atomicAdd(&c2[i2], 1);
    __syncthreads();
    if (t < 64) { g_bc1T[t * 64 + blk] = c1[t]; g_bc2T[t * 64 + blk] = c2[t]; }
}

// ---------------- rescue stage 1: exact fp32 logits for flagged tokens ----------------
// grid 4096: block = (expert group eg = b&7 [8 experts], token stripe ts = b>>3 [of 512])
// warp w computes expert eg*8+w; writes exact logits back into g_logits rows.
__global__ __launch_bounds__(256)
void rescue_logits(const float* __restrict__ X, const float* __restrict__ W) {
    const int b = blockIdx.x;
    const int eg = b & 7, ts = b >> 3;
    const int warp = threadIdx.x >> 5, lane = threadIdx.x & 31;
    const int e = eg * 8 + warp;
    const int nf = g_nflag;
    const float4* wr = (const float4*)(W + (size_t)e * D_DIM);

    for (int fi = ts; fi < nf; fi += 512) {
        const int i = g_flagged[fi];
        const float4* xr = (const float4*)(X + (size_t)i * D_DIM);
        float a0 = 0.f, a1 = 0.f, a2 = 0.f, a3 = 0.f;
#pragma unroll
        for (int j = 0; j < 32; ++j) {
            const float4 xa = xr[j * 32 + lane];
            const float4 wa = wr[j * 32 + lane];
            a0 = fmaf(xa.x, wa.x, a0);
            a1 = fmaf(xa.y, wa.y, a1);
            a2 = fmaf(xa.z, wa.z, a2);
            a3 = fmaf(xa.w, wa.w, a3);
        }
        float tot = ((a0 + a1) + a2) + a3;
#pragma unroll
        for (int off = 16; off; off >>= 1)
            tot += __shfl_xor_sync(0xffffffffu, tot, off);
        if (lane == 0) g_logits[(size_t)i * 64 + e] = tot;
    }
}

// ---------------- rescue stage 2: decisions + histogram patch (warp per token) ----------------
__global__ __launch_bounds__(256)
void rescue_decide() {
    const int warp = threadIdx.x >> 5, lane = threadIdx.x & 31;
    const int nf = g_nflag;

    for (int fi = blockIdx.x * 8 + warp; fi < nf; fi += gridDim.x * 8) {
        const int i = g_flagged[fi];
        const float l0 = g_logits[(size_t)i * 64 + lane];
        const float l1 = g_logits[(size_t)i * 64 + 32 + lane];
        const float NEG_INF = __int_as_float(0xff800000);

        float v; int idx;
        if (l1 > l0) { v = l1; idx = lane + 32; } else { v = l0; idx = lane; }
#pragma unroll
        for (int off = 16; off; off >>= 1) {
            float ov = __shfl_xor_sync(0xffffffffu, v, off);
            int   oi = __shfl_xor_sync(0xffffffffu, idx, off);
            if (ov > v || (ov == v && oi < idx)) { v = ov; idx = oi; }
        }
        const float mm = v; const int i1 = idx;

        float w0 = (lane == i1) ? NEG_INF : l0;
        float w1 = (lane + 32 == i1) ? NEG_INF : l1;
        float v2; int idx2;
        if (w1 > w0) { v2 = w1; idx2 = lane + 32; } else { v2 = w0; idx2 = lane; }
#pragma unroll
        for (int off = 16; off; off >>= 1) {
            float ov = __shfl_xor_sync(0xffffffffu, v2, off);
            int   oi = __shfl_xor_sync(0xffffffffu, idx2, off);
            if (ov > v2 || (ov == v2 && oi < idx2)) { v2 = ov; idx2 = oi; }
        }

        float s = expf(l0 - mm) + expf(l1 - mm);
#pragma unroll
        for (int off = 16; off; off >>= 1)
            s += __shfl_xor_sync(0xffffffffu, s, off);

        if (lane == 0) {
            const float g1 = 1.0f / s;
            const float g2 = expf(v2 - mm) / s;
            const float denom = g1 + g2;
            const float g2n = g2 / denom;
            const float rnd = jax_uniform_partitionable((uint32_t)i);
            const int w2 = (rnd < 2.0f * g2n) ? 1 : 0;

            const int blkb = i >> 8;
            const int oe1 = g_e1[i], oe2 = g_e2[i], ow2 = g_want2[i];
            if (i1 != oe1) {
                atomicSub(&g_bc1T[oe1 * 64 + blkb], 1);
                atomicAdd(&g_bc1T[i1 * 64 + blkb], 1);
            }
            if (ow2) atomicSub(&g_bc2T[oe2 * 64 + blkb], 1);
            if (w2)  atomicAdd(&g_bc2T[idx2 * 64 + blkb], 1);

            g_e1[i] = i1;
            g_e2[i] = idx2;
            g_g1n[i] = g1 / denom;
            g_g2n[i] = g2n;
            g_want2[i] = w2;
        }
    }
}

// ---------------- cross-block scan (transposed, int4) ----------------
__global__ void scan_kernel() {
    const int e = threadIdx.x;
    if (e >= 64) return;
    int4 buf[16];
    const int4* s1 = (const int4*)(g_bc1T + e * 64);
#pragma unroll
    for (int q = 0; q < 16; ++q) buf[q] = s1[q];
    int r1 = 0;
#pragma unroll
    for (int q = 0; q < 16; ++q) {
        g_base1T[e * 64 + q * 4 + 0] = r1; r1 += buf[q].x;
        g_base1T[e * 64 + q * 4 + 1] = r1; r1 += buf[q].y;
        g_base1T[e * 64 + q * 4 + 2] = r1; r1 += buf[q].z;
        g_base1T[e * 64 + q * 4 + 3] = r1; r1 += buf[q].w;
    }
    const int4* s2 = (const int4*)(g_bc2T + e * 64);
#pragma unroll
    for (int q = 0; q < 16; ++q) buf[q] = s2[q];
    int r2 = 0;
#pragma unroll
    for (int q = 0; q < 16; ++q) {
        g_base2T[e * 64 + q * 4 + 0] = r2; r2 += buf[q].x;
        g_base2T[e * 64 + q * 4 + 1] = r2; r2 += buf[q].y;
        g_base2T[e * 64 + q * 4 + 2] = r2; r2 += buf[q].z;
        g_base2T[e * 64 + q * 4 + 3] = r2; r2 += buf[q].w;
    }
    g_cap2[e] = CAP - (r1 < CAP ? r1 : CAP);
}

// ---------------- final ranks + full-row write (zeroing fused) ----------------
__global__ __launch_bounds__(256)
void assign_kernel(float* __restrict__ out) {
    __shared__ int wc1[8][64];
    __shared__ int wc2[8][64];
    const int t = threadIdx.x, warp = t >> 5, lane = t & 31;
    const int blk = blockIdx.x;

    ((int*)wc1)[t] = 0; ((int*)wc1)[t + 256] = 0;
    ((int*)wc2)[t] = 0; ((int*)wc2)[t + 256] = 0;
    __syncthreads();

    const int i  = blk * 256 + t;
    const int e1 = g_e1[i], e2 = g_e2[i], want2 = g_want2[i];
    const unsigned lt = (1u << lane) - 1u;

    const unsigned m1 = __match_any_sync(0xffffffffu, e1);
    const int lr1 = __popc(m1 & lt);
    if (lr1 == 0) wc1[warp][e1] = __popc(m1);

    const unsigned act2 = __ballot_sync(0xffffffffu, want2);
    const unsigned m2 = __match_any_sync(0xffffffffu, e2) & act2;
    const int lr2 = __popc(m2 & lt);
    if (want2 && lr2 == 0) wc2[warp][e2] = __popc(m2);
    __syncthreads();

    int off1 = 0, off2 = 0;
    for (int w = 0; w < warp; ++w) {
        off1 += wc1[w][e1];
        off2 += wc2[w][e2];
    }

    const int pos1 = g_base1T[e1 * 64 + blk] + off1 + lr1 + 1;
    const int pos2 = g_base2T[e2 * 64 + blk] + off2 + lr2 + 1;
    const float val1 = (pos1 <= CAP) ? g_g1n[i] : 0.f;
    const float val2 = (want2 && pos2 <= g_cap2[e2]) ? g_g2n[i] : 0.f;

    float4* op = (float4*)(out + (size_t)i * 64);
#pragma unroll
    for (int q = 0; q < 16; ++q) {
        float4 z = make_float4(0.f, 0.f, 0.f, 0.f);
        if ((e1 >> 2) == q) ((float*)&z)[e1 & 3] = val1;
        if ((e2 >> 2) == q) ((float*)&z)[e2 & 3] = val2;
        op[q] = z;
    }
}

// ---------------- launcher ----------------
extern "C" void kernel_launch(void* const* d_in, const int* in_sizes, int n_in,
                              void* d_out, int out_size) {
    const float* x = (const float*)d_in[0];
    const float* w = (const float*)d_in[1];
    float* out = (float*)d_out;

    cudaFuncSetAttribute(gemm_mma, cudaFuncAttributeMaxDynamicSharedMemorySize, GEMM_SMEM);

    wconv_kernel<<<512, 256>>>(w);
    gemm_mma<<<S_TOK / BM, 512, GEMM_SMEM>>>(x);
    topk256<<<S_TOK / 256, 256>>>();
    rescue_logits<<<4096, 256>>>(x, w);
    rescue_decide<<<512, 256>>>();
    scan_kernel<<<1, 64>>>();
    assign_kernel<<<S_TOK / 256, 256>>>(out);
}

// round 11
// speedup vs baseline: 1.3719x; 1.3719x over previous
#include <cuda_runtime.h>
#include <cuda_fp16.h>
#include <cstdint>

#define S_TOK 16384
#define D_DIM 4096
#define N_EXP 64
#define CAP   320
#define KC    64
#define NCHUNK 64
#define BM    128

#define SWZ(o) ((o) ^ (((o) >> 3) & 0x70))

// ---------------- scratch ----------------
__device__ float g_logits[S_TOK * N_EXP];
__device__ __align__(16) uint32_t g_whT[NCHUNK * 2304];
__device__ int   g_e1[S_TOK];
__device__ int   g_e2[S_TOK];
__device__ int   g_want2[S_TOK];
__device__ float g_g1n[S_TOK];
__device__ float g_g2n[S_TOK];
__device__ int   g_bc1T[64 * 64];    // [expert][block]
__device__ int   g_bc2T[64 * 64];
__device__ int   g_base1T[64 * 64];
__device__ int   g_base2T[64 * 64];
__device__ int   g_cap2[64];
__device__ int   g_nflag;
__device__ int   g_flagged[S_TOK];

// ---------------- PTX helpers ----------------
__device__ __forceinline__ uint32_t smem_to_u32(const void* p) {
    uint32_t a;
    asm("{ .reg .u64 t; cvta.to.shared.u64 t, %1; cvt.u32.u64 %0, t; }" : "=r"(a) : "l"(p));
    return a;
}
#define CP_ASYNC16(dst, src) \
    asm volatile("cp.async.cg.shared.global [%0], [%1], 16;" :: "r"(dst), "l"(src) : "memory")
#define CP_ASYNC_COMMIT()  asm volatile("cp.async.commit_group;" ::: "memory")
#define CP_ASYNC_WAIT0()   asm volatile("cp.async.wait_group 0;" ::: "memory")

#define LDSM_X4(r0, r1, r2, r3, addr) \
    asm volatile("ldmatrix.sync.aligned.m8n8.x4.shared.b16 {%0,%1,%2,%3}, [%4];" \
        : "=r"(r0), "=r"(r1), "=r"(r2), "=r"(r3) : "r"(addr))

#define LDS32(r, addr) \
    asm volatile("ld.shared.b32 %0, [%1];" : "=r"(r) : "r"(addr))

#define MMA_FP16(d, a, b0, b1) \
    asm volatile("mma.sync.aligned.m16n8k16.row.col.f32.f16.f16.f32 " \
        "{%0,%1,%2,%3}, {%4,%5,%6,%7}, {%8,%9}, {%0,%1,%2,%3};" \
        : "+f"((d)[0]), "+f"((d)[1]), "+f"((d)[2]), "+f"((d)[3]) \
        : "r"((a)[0]), "r"((a)[1]), "r"((a)[2]), "r"((a)[3]), "r"(b0), "r"(b1))

// gemm smem layout
#define XS(s)  (sb + (s) * 16384)
#define WHS(s) (sb + 32768 + (s) * 9216)
#define GEMM_SMEM 51200

// ---------------- W pre-conversion (also resets flag counter) ----------------
__global__ __launch_bounds__(256)
void wconv_kernel(const float* __restrict__ W) {
    const int pid = blockIdx.x * 256 + threadIdx.x;   // 0..131071
    if (pid == 0) g_nflag = 0;
    const int n = pid >> 11;                          // expert 0..63
    const int j = pid & 2047;                         // k-pair 0..2047
    const float2 v = *(const float2*)(W + (size_t)n * D_DIM + j * 2);
    const __half h0 = __float2half_rn(v.x);
    const __half h1 = __float2half_rn(v.y);
    const uint32_t hp = (uint32_t)__half_as_ushort(h0) | ((uint32_t)__half_as_ushort(h1) << 16);
    g_whT[(j >> 5) * 2304 + n * 36 + (j & 31)] = hp;
}

// ---------------- HMMA GEMM: single fp16 product ----------------
__global__ __launch_bounds__(512, 1)
void gemm_mma(const float* __restrict__ X) {
    extern __shared__ __align__(1024) char smem[];
    const uint32_t sb = smem_to_u32(smem);
    const int tid = threadIdx.x, wid = tid >> 5, lane = tid & 31;
    const int m0 = blockIdx.x * BM;
    const int warp_m = wid & 3, warp_n = wid >> 2;   // 4M x 4N, warp tile m32 x n16

    float acc[2][2][4];
#pragma unroll
    for (int a = 0; a < 2; ++a)
#pragma unroll
        for (int b = 0; b < 2; ++b)
#pragma unroll
            for (int q = 0; q < 4; ++q) acc[a][b][q] = 0.f;

    const int xrow = tid >> 2, xc4 = tid & 3;
    const float4* xp = (const float4*)(X + (size_t)(m0 + xrow) * D_DIM);

    const uint32_t a_b0  = (uint32_t)((warp_m * 32 + (lane & 15)) * 128 + (lane >> 4) * 16);
    const uint32_t b_off = (uint32_t)((warp_n * 16 + (lane >> 2)) * 144 + (lane & 3) * 4);

    auto loadB = [&](int c, int s) {
        const char* gh = (const char*)(g_whT + c * 2304);
        const uint32_t wh = WHS(s);
        CP_ASYNC16(wh + tid * 16, gh + tid * 16);
        if (tid < 64) CP_ASYNC16(wh + (512 + tid) * 16, gh + (512 + tid) * 16);
    };
    auto loadx = [&](int c, float4* v) {
#pragma unroll
        for (int it = 0; it < 4; ++it)
            v[it] = xp[c * 16 + xc4 + it * 4];
    };
    auto storeXS = [&](int s, const float4* v) {
        const uint32_t xs = XS(s);
#pragma unroll
        for (int it = 0; it < 4; ++it) {
            const __half2 h01 = __floats2half2_rn(v[it].x, v[it].y);
            const __half2 h23 = __floats2half2_rn(v[it].z, v[it].w);
            const uint32_t p0 = *(const uint32_t*)&h01;
            const uint32_t p1 = *(const uint32_t*)&h23;
            const uint32_t off = SWZ((uint32_t)(xrow * 128 + (xc4 + it * 4) * 8));
            asm volatile("st.shared.v2.b32 [%0], {%1,%2};" :: "r"(xs + off), "r"(p0), "r"(p1) : "memory");
        }
    };

    // prologue
    float4 v[4];
    loadB(0, 0);
    CP_ASYNC_COMMIT();
    loadx(0, v);
    storeXS(0, v);
    CP_ASYNC_WAIT0();
    __syncthreads();

    for (int c = 0; c < NCHUNK; ++c) {
        const int s = c & 1;
        float4 nv[4];
        if (c + 1 < NCHUNK) {
            loadB(c + 1, s ^ 1);
            CP_ASYNC_COMMIT();
            loadx(c + 1, nv);
        }
        const uint32_t xs = XS(s), wh = WHS(s);
#pragma unroll
        for (int ks = 0; ks < 4; ++ks) {
            uint32_t ah[2][4];
            LDSM_X4(ah[0][0], ah[0][1], ah[0][2], ah[0][3], xs + SWZ(a_b0 + ks * 32));
            LDSM_X4(ah[1][0], ah[1][1], ah[1][2], ah[1][3], xs + SWZ(a_b0 + 2048 + ks * 32));
            uint32_t bh[2][2];
#pragma unroll
            for (int nt = 0; nt < 2; ++nt) {
                const uint32_t bo = b_off + nt * 1152 + ks * 32;
                LDS32(bh[nt][0], wh + bo);
                LDS32(bh[nt][1], wh + bo + 16);
            }
#pragma unroll
            for (int mt = 0; mt < 2; ++mt)
#pragma unroll
                for (int nt = 0; nt < 2; ++nt)
                    MMA_FP16(acc[mt][nt], ah[mt], bh[nt][0], bh[nt][1]);
        }
        if (c + 1 < NCHUNK) storeXS(s ^ 1, nv);
        CP_ASYNC_WAIT0();
        __syncthreads();
    }

    const int r0 = m0 + warp_m * 32 + (lane >> 2);
    const int c0 = warp_n * 16 + (lane & 3) * 2;
#pragma unroll
    for (int mt = 0; mt < 2; ++mt)
#pragma unroll
        for (int nt = 0; nt < 2; ++nt) {
            const int r = r0 + mt * 16, cc = c0 + nt * 8;
            *(float2*)&g_logits[(size_t)r * 64 + cc]       = make_float2(acc[mt][nt][0], acc[mt][nt][1]);
            *(float2*)&g_logits[(size_t)(r + 8) * 64 + cc] = make_float2(acc[mt][nt][2], acc[mt][nt][3]);
        }
}

// ---------------- Threefry-2x32 (JAX partitionable, key(1)) ----------------
__device__ __forceinline__ void threefry2x32(uint32_t x0, uint32_t x1,
                                             uint32_t& o0, uint32_t& o1) {
    const uint32_t k0 = 0u, k1 = 1u, k2 = 0x1BD11BDBu;
    x0 += k0; x1 += k1;
#define TFR(r) { x0 += x1; x1 = (x1 << (r)) | (x1 >> (32 - (r))); x1 ^= x0; }
    TFR(13) TFR(15) TFR(26) TFR(6)  x0 += k1; x1 += k2 + 1u;
    TFR(17) TFR(29) TFR(16) TFR(24) x0 += k2; x1 += k0 + 2u;
    TFR(13) TFR(15) TFR(26) TFR(6)  x0 += k0; x1 += k1 + 3u;
    TFR(17) TFR(29) TFR(16) TFR(24) x0 += k1; x1 += k2 + 4u;
    TFR(13) TFR(15) TFR(26) TFR(6)  x0 += k2; x1 += k0 + 5u;
#undef TFR
    o0 = x0; o1 = x1;
}
__device__ __forceinline__ float jax_uniform_partitionable(uint32_t i) {
    uint32_t o0, o1;
    threefry2x32(0u, i, o0, o1);
    const uint32_t bits = o0 ^ o1;
    return __uint_as_float((bits >> 9) | 0x3f800000u) - 1.0f;
}

// ---------------- fused topk + softmax + want2 + flags + block histogram ----------------
__global__ __launch_bounds__(256)
void topk256() {
    __shared__ int c1[64], c2[64];
    const int t = threadIdx.x, blk = blockIdx.x;
    const int i = blk * 256 + t;
    if (t < 64) { c1[t] = 0; c2[t] = 0; }
    __syncthreads();

    float4 L[16];
    const float4* lp = (const float4*)(g_logits + (size_t)i * 64);
#pragma unroll
    for (int q = 0; q < 16; ++q) L[q] = lp[q];

    float v1 = -3.4e38f, v2 = -3.4e38f, v3 = -3.4e38f;
    int i1 = 0, i2 = 0;
#pragma unroll
    for (int q = 0; q < 16; ++q) {
        const float e[4] = {L[q].x, L[q].y, L[q].z, L[q].w};
#pragma unroll
        for (int r = 0; r < 4; ++r) {
            const float x = e[r]; const int idx = q * 4 + r;
            if (x > v1)      { v3 = v2; v2 = v1; i2 = i1; v1 = x; i1 = idx; }
            else if (x > v2) { v3 = v2; v2 = x; i2 = idx; }
            else if (x > v3) { v3 = x; }
        }
    }
    float s = 0.f;
#pragma unroll
    for (int q = 0; q < 16; ++q)
        s += expf(L[q].x - v1) + expf(L[q].y - v1) + expf(L[q].z - v1) + expf(L[q].w - v1);

    const float g1 = 1.0f / s;
    const float g2 = expf(v2 - v1) / s;
    const float denom = g1 + g2;
    const float g1n = g1 / denom, g2n = g2 / denom;
    const float rnd = jax_uniform_partitionable((uint32_t)i);
    const int want2 = (rnd < 2.0f * g2n) ? 1 : 0;

    g_e1[i] = i1; g_e2[i] = i2;
    g_g1n[i] = g1n; g_g2n[i] = g2n;
    g_want2[i] = want2;

    const float TAU_GAP = 2e-3f, TAU_RND = 1.2e-3f;
    if ((v1 - v2) < TAU_GAP || (v2 - v3) < TAU_GAP || fabsf(rnd - 2.0f * g2n) < TAU_RND) {
        const int k = atomicAdd(&g_nflag, 1);
        g_flagged[k] = i;
    }
    atomicAdd(&c1[i1], 1);
    if (want2) atomicAdd(&c2[i2], 1);
    __syncthreads();
    if (t < 64) { g_bc1T[t * 64 + blk] = c1[t]; g_bc2T[t * 64 + blk] = c2[t]; }
}

// ---------------- exact rescue: candidates-only, warp per flagged token ----------------
// Decisions & output values depend only on top-2 identities and (v1 - v2):
// g1n = 1/(1+exp(v2-v1)), g2n = exp(v2-v1)/(1+exp(v2-v1)).  Recompute exact fp32
// logits ONLY for experts within TAU_C of approx-v2 (typically 2-3 candidates).
__global__ __launch_bounds__(256)
void rescue_exact(const float* __restrict__ X, const float* __restrict__ W) {
    const int warp = threadIdx.x >> 5, lane = threadIdx.x & 31;
    const int gwarp = blockIdx.x * 8 + warp;
    const int nwarps = gridDim.x * 8;
    const int nf = g_nflag;

    for (int fi = gwarp; fi < nf; fi += nwarps) {
        const int i = g_flagged[fi];
        const float* row = g_logits + (size_t)i * 64;
        const float l0 = row[lane];
        const float l1 = row[lane + 32];
        const float v2a = row[g_e2[i]];          // approx 2nd-best (broadcast load)

        // candidate mask: experts with approx logit > v2a - TAU_C (9 sigma of fp16 noise)
        const float TAU_C = 2.5e-3f;
        const float thr = v2a - TAU_C;
        const unsigned mlo = __ballot_sync(0xffffffffu, l0 > thr);
        const unsigned mhi = __ballot_sync(0xffffffffu, l1 > thr);
        uint64_t cmask = ((uint64_t)mhi << 32) | (uint64_t)mlo;

        const float4* xr = (const float4*)(X + (size_t)i * D_DIM);

        float v1e = -3.4e38f, v2e = -3.4e38f;
        int i1e = 0, i2e = 0;
        while (cmask) {
            const int c = __ffsll((long long)cmask) - 1;   // ascending index order
            cmask &= cmask - 1;
            const float4* wr = (const float4*)(W + (size_t)c * D_DIM);
            float a0 = 0.f, a1 = 0.f, a2 = 0.f, a3 = 0.f;
#pragma unroll
            for (int j = 0; j < 32; ++j) {
                const float4 xa = xr[j * 32 + lane];
                const float4 wa = wr[j * 32 + lane];
                a0 = fmaf(xa.x, wa.x, a0);
                a1 = fmaf(xa.y, wa.y, a1);
                a2 = fmaf(xa.z, wa.z, a2);
                a3 = fmaf(xa.w, wa.w, a3);
            }
            float tot = ((a0 + a1) + a2) + a3;
#pragma unroll
            for (int off = 16; off; off >>= 1)
                tot += __shfl_xor_sync(0xffffffffu, tot, off);
            // ascending-index scan + strict '>' == jax tiebreak (ties -> lower index)
            if (tot > v1e)      { v2e = v1e; i2e = i1e; v1e = tot; i1e = c; }
            else if (tot > v2e) { v2e = tot; i2e = c; }
        }

        if (lane == 0) {
            const float t = expf(v2e - v1e);
            const float g1n = 1.0f / (1.0f + t);
            const float g2n = t / (1.0f + t);
            const float rnd = jax_uniform_partitionable((uint32_t)i);
            const int w2 = (rnd < 2.0f * g2n) ? 1 : 0;

            const int blkb = i >> 8;
            const int oe1 = g_e1[i], oe2 = g_e2[i], ow2 = g_want2[i];
            if (i1e != oe1) {
                atomicSub(&g_bc1T[oe1 * 64 + blkb], 1);
                atomicAdd(&g_bc1T[i1e * 64 + blkb], 1);
            }
            if (ow2) atomicSub(&g_bc2T[oe2 * 64 + blkb], 1);
            if (w2)  atomicAdd(&g_bc2T[i2e * 64 + blkb], 1);

            g_e1[i] = i1e;
            g_e2[i] = i2e;
            g_g1n[i] = g1n;
            g_g2n[i] = g2n;
            g_want2[i] = w2;
        }
    }
}

// ---------------- cross-block scan (transposed, int4) ----------------
__global__ void scan_kernel() {
    const int e = threadIdx.x;
    if (e >= 64) return;
    int4 buf[16];
    const int4* s1 = (const int4*)(g_bc1T + e * 64);
#pragma unroll
    for (int q = 0; q < 16; ++q) buf[q] = s1[q];
    int r1 = 0;
#pragma unroll
    for (int q = 0; q < 16; ++q) {
        g_base1T[e * 64 + q * 4 + 0] = r1; r1 += buf[q].x;
        g_base1T[e * 64 + q * 4 + 1] = r1; r1 += buf[q].y;
        g_base1T[e * 64 + q * 4 + 2] = r1; r1 += buf[q].z;
        g_base1T[e * 64 + q * 4 + 3] = r1; r1 += buf[q].w;
    }
    const int4* s2 = (const int4*)(g_bc2T + e * 64);
#pragma unroll
    for (int q = 0; q < 16; ++q) buf[q] = s2[q];
    int r2 = 0;
#pragma unroll
    for (int q = 0; q < 16; ++q) {
        g_base2T[e * 64 + q * 4 + 0] = r2; r2 += buf[q].x;
        g_base2T[e * 64 + q * 4 + 1] = r2; r2 += buf[q].y;
        g_base2T[e * 64 + q * 4 + 2] = r2; r2 += buf[q].z;
        g_base2T[e * 64 + q * 4 + 3] = r2; r2 += buf[q].w;
    }
    g_cap2[e] = CAP - (r1 < CAP ? r1 : CAP);
}

// ---------------- final ranks + full-row write (zeroing fused) ----------------
__global__ __launch_bounds__(256)
void assign_kernel(float* __restrict__ out) {
    __shared__ int wc1[8][64];
    __shared__ int wc2[8][64];
    const int t = threadIdx.x, warp = t >> 5, lane = t & 31;
    const int blk = blockIdx.x;

    ((int*)wc1)[t] = 0; ((int*)wc1)[t + 256] = 0;
    ((int*)wc2)[t] = 0; ((int*)wc2)[t + 256] = 0;
    __syncthreads();

    const int i  = blk * 256 + t;
    const int e1 = g_e1[i], e2 = g_e2[i], want2 = g_want2[i];
    const unsigned lt = (1u << lane) - 1u;

    const unsigned m1 = __match_any_sync(0xffffffffu, e1);
    const int lr1 = __popc(m1 & lt);
    if (lr1 == 0) wc1[warp][e1] = __popc(m1);

    const unsigned act2 = __ballot_sync(0xffffffffu, want2);
    const unsigned m2 = __match_any_sync(0xffffffffu, e2) & act2;
    const int lr2 = __popc(m2 & lt);
    if (want2 && lr2 == 0) wc2[warp][e2] = __popc(m2);
    __syncthreads();

    int off1 = 0, off2 = 0;
    for (int w = 0; w < warp; ++w) {
        off1 += wc1[w][e1];
        off2 += wc2[w][e2];
    }

    const int pos1 = g_base1T[e1 * 64 + blk] + off1 + lr1 + 1;
    const int pos2 = g_base2T[e2 * 64 + blk] + off2 + lr2 + 1;
    const float val1 = (pos1 <= CAP) ? g_g1n[i] : 0.f;
    const float val2 = (want2 && pos2 <= g_cap2[e2]) ? g_g2n[i] : 0.f;

    float4* op = (float4*)(out + (size_t)i * 64);
#pragma unroll
    for (int q = 0; q < 16; ++q) {
        float4 z = make_float4(0.f, 0.f, 0.f, 0.f);
        if ((e1 >> 2) == q) ((float*)&z)[e1 & 3] = val1;
        if ((e2 >> 2) == q) ((float*)&z)[e2 & 3] = val2;
        op[q] = z;
    }
}

// ---------------- launcher ----------------
extern "C" void kernel_launch(void* const* d_in, const int* in_sizes, int n_in,
                              void* d_out, int out_size) {
    const float* x = (const float*)d_in[0];
    const float* w = (const float*)d_in[1];
    float* out = (float*)d_out;

    cudaFuncSetAttribute(gemm_mma, cudaFuncAttributeMaxDynamicSharedMemorySize, GEMM_SMEM);

    wconv_kernel<<<512, 256>>>(w);
    gemm_mma<<<S_TOK / BM, 512, GEMM_SMEM>>>(x);
    topk256<<<S_TOK / 256, 256>>>();
    rescue_exact<<<256, 256>>>(x, w);
    scan_kernel<<<1, 64>>>();
    assign_kernel<<<S_TOK / 256, 256>>>(out);
}

// round 12
// speedup vs baseline: 1.5225x; 1.1098x over previous
#include <cuda_runtime.h>
#include <cuda_fp16.h>
#include <cstdint>

#define S_TOK 16384
#define D_DIM 4096
#define N_EXP 64
#define CAP   320
#define NCHUNK2 32               // outer iterations, 128 K-elems each
#define BM    128

#define SWZ(o) ((o) ^ (((o) >> 3) & 0x70))

// ---------------- scratch ----------------
__device__ float g_logits[S_TOK * N_EXP];
__device__ __align__(16) uint32_t g_whT[64 * 2304];
__device__ int   g_e1[S_TOK];
__device__ int   g_e2[S_TOK];
__device__ int   g_want2[S_TOK];
__device__ float g_g1n[S_TOK];
__device__ float g_g2n[S_TOK];
__device__ int   g_bc1T[64 * 128];   // [expert][128-token block]
__device__ int   g_bc2T[64 * 128];
__device__ int   g_base1T[64 * 128];
__device__ int   g_base2T[64 * 128];
__device__ int   g_cap2[64];
__device__ int   g_nflag;
__device__ int   g_flagged[S_TOK];

// ---------------- PTX helpers ----------------
__device__ __forceinline__ uint32_t smem_to_u32(const void* p) {
    uint32_t a;
    asm("{ .reg .u64 t; cvta.to.shared.u64 t, %1; cvt.u32.u64 %0, t; }" : "=r"(a) : "l"(p));
    return a;
}
#define CP_ASYNC16(dst, src) \
    asm volatile("cp.async.cg.shared.global [%0], [%1], 16;" :: "r"(dst), "l"(src) : "memory")
#define CP_ASYNC_COMMIT()  asm volatile("cp.async.commit_group;" ::: "memory")
#define CP_ASYNC_WAIT0()   asm volatile("cp.async.wait_group 0;" ::: "memory")

#define LDSM_X4(r0, r1, r2, r3, addr) \
    asm volatile("ldmatrix.sync.aligned.m8n8.x4.shared.b16 {%0,%1,%2,%3}, [%4];" \
        : "=r"(r0), "=r"(r1), "=r"(r2), "=r"(r3) : "r"(addr))

#define LDS32(r, addr) \
    asm volatile("ld.shared.b32 %0, [%1];" : "=r"(r) : "r"(addr))

#define MMA_FP16(d, a, b0, b1) \
    asm volatile("mma.sync.aligned.m16n8k16.row.col.f32.f16.f16.f32 " \
        "{%0,%1,%2,%3}, {%4,%5,%6,%7}, {%8,%9}, {%0,%1,%2,%3};" \
        : "+f"((d)[0]), "+f"((d)[1]), "+f"((d)[2]), "+f"((d)[3]) \
        : "r"((a)[0]), "r"((a)[1]), "r"((a)[2]), "r"((a)[3]), "r"(b0), "r"(b1))

// gemm smem layout: XS stage = 2 sub-tiles of 16KB; WHS stage = 2 sub-tiles of 9216B
#define XS(s)  (sb + (s) * 32768)
#define WHS(s) (sb + 65536 + (s) * 18432)
#define GEMM_SMEM 102400

// ---------------- Threefry-2x32 (JAX partitionable, key(1)) ----------------
__device__ __forceinline__ void threefry2x32(uint32_t x0, uint32_t x1,
                                             uint32_t& o0, uint32_t& o1) {
    const uint32_t k0 = 0u, k1 = 1u, k2 = 0x1BD11BDBu;
    x0 += k0; x1 += k1;
#define TFR(r) { x0 += x1; x1 = (x1 << (r)) | (x1 >> (32 - (r))); x1 ^= x0; }
    TFR(13) TFR(15) TFR(26) TFR(6)  x0 += k1; x1 += k2 + 1u;
    TFR(17) TFR(29) TFR(16) TFR(24) x0 += k2; x1 += k0 + 2u;
    TFR(13) TFR(15) TFR(26) TFR(6)  x0 += k0; x1 += k1 + 3u;
    TFR(17) TFR(29) TFR(16) TFR(24) x0 += k1; x1 += k2 + 4u;
    TFR(13) TFR(15) TFR(26) TFR(6)  x0 += k2; x1 += k0 + 5u;
#undef TFR
    o0 = x0; o1 = x1;
}
__device__ __forceinline__ float jax_uniform_partitionable(uint32_t i) {
    uint32_t o0, o1;
    threefry2x32(0u, i, o0, o1);
    const uint32_t bits = o0 ^ o1;
    return __uint_as_float((bits >> 9) | 0x3f800000u) - 1.0f;
}

// ---------------- W pre-conversion (also resets flag counter) ----------------
__global__ __launch_bounds__(256)
void wconv_kernel(const float* __restrict__ W) {
    const int pid = blockIdx.x * 256 + threadIdx.x;   // 0..131071
    if (pid == 0) g_nflag = 0;
    const int n = pid >> 11;                          // expert 0..63
    const int j = pid & 2047;                         // k-pair 0..2047
    const float2 v = *(const float2*)(W + (size_t)n * D_DIM + j * 2);
    const __half h0 = __float2half_rn(v.x);
    const __half h1 = __float2half_rn(v.y);
    const uint32_t hp = (uint32_t)__half_as_ushort(h0) | ((uint32_t)__half_as_ushort(h1) << 16);
    g_whT[(j >> 5) * 2304 + n * 36 + (j & 31)] = hp;
}

// ---------------- fused GEMM + topk/softmax/want2/flag/histogram ----------------
__global__ __launch_bounds__(512, 1)
void gemm_fused(const float* __restrict__ X) {
    extern __shared__ __align__(1024) char smem[];
    const uint32_t sb = smem_to_u32(smem);
    const int tid = threadIdx.x, wid = tid >> 5, lane = tid & 31;
    const int m0 = blockIdx.x * BM;
    const int warp_m = wid & 3, warp_n = wid >> 2;   // 4M x 4N, warp tile m32 x n16

    float acc[2][2][4];
#pragma unroll
    for (int a = 0; a < 2; ++a)
#pragma unroll
        for (int b = 0; b < 2; ++b)
#pragma unroll
            for (int q = 0; q < 4; ++q) acc[a][b][q] = 0.f;

    const int xrow = tid >> 2, xc4 = tid & 3;
    const float4* xp = (const float4*)(X + (size_t)(m0 + xrow) * D_DIM);

    const uint32_t a_b0  = (uint32_t)((warp_m * 32 + (lane & 15)) * 128 + (lane >> 4) * 16);
    const uint32_t b_off = (uint32_t)((warp_n * 16 + (lane >> 2)) * 144 + (lane & 3) * 4);

    auto loadB = [&](int c2, int s) {
        const char* g0 = (const char*)(g_whT + (2 * c2) * 2304);
        const char* g1 = (const char*)(g_whT + (2 * c2 + 1) * 2304);
        const uint32_t wh = WHS(s);
        CP_ASYNC16(wh + tid * 16, g0 + tid * 16);
        CP_ASYNC16(wh + 9216 + tid * 16, g1 + tid * 16);
        if (tid < 64) {
            CP_ASYNC16(wh + (512 + tid) * 16, g0 + (512 + tid) * 16);
            CP_ASYNC16(wh + 9216 + (512 + tid) * 16, g1 + (512 + tid) * 16);
        }
    };
    auto loadx = [&](int c2, float4* v) {
#pragma unroll
        for (int it = 0; it < 8; ++it)
            v[it] = xp[c2 * 32 + xc4 + it * 4];
    };
    auto storeXS = [&](int s, const float4* v) {
        const uint32_t xs = XS(s);
#pragma unroll
        for (int it = 0; it < 8; ++it) {
            const __half2 h01 = __floats2half2_rn(v[it].x, v[it].y);
            const __half2 h23 = __floats2half2_rn(v[it].z, v[it].w);
            const uint32_t p0 = *(const uint32_t*)&h01;
            const uint32_t p1 = *(const uint32_t*)&h23;
            const int col4 = xc4 + it * 4;               // 0..31 within 128-col pair
            const int sub = col4 >> 4;
            const uint32_t off = (uint32_t)(sub * 16384) +
                                 SWZ((uint32_t)(xrow * 128 + (col4 & 15) * 8));
            asm volatile("st.shared.v2.b32 [%0], {%1,%2};" :: "r"(xs + off), "r"(p0), "r"(p1) : "memory");
        }
    };

    // prologue
    float4 v[8];
    loadB(0, 0);
    CP_ASYNC_COMMIT();
    loadx(0, v);
    storeXS(0, v);
    CP_ASYNC_WAIT0();
    __syncthreads();

    for (int c2 = 0; c2 < NCHUNK2; ++c2) {
        const int s = c2 & 1;
        float4 nv[8];
        if (c2 + 1 < NCHUNK2) {
            loadB(c2 + 1, s ^ 1);
            CP_ASYNC_COMMIT();
            loadx(c2 + 1, nv);
        }
#pragma unroll
        for (int ks = 0; ks < 8; ++ks) {
            const int sub = ks >> 2, ksl = ks & 3;
            const uint32_t xs = XS(s) + sub * 16384;
            const uint32_t wh = WHS(s) + sub * 9216;
            uint32_t ah[2][4];
            LDSM_X4(ah[0][0], ah[0][1], ah[0][2], ah[0][3], xs + SWZ(a_b0 + ksl * 32));
            LDSM_X4(ah[1][0], ah[1][1], ah[1][2], ah[1][3], xs + SWZ(a_b0 + 2048 + ksl * 32));
            uint32_t bh[2][2];
#pragma unroll
            for (int nt = 0; nt < 2; ++nt) {
                const uint32_t bo = b_off + nt * 1152 + ksl * 32;
                LDS32(bh[nt][0], wh + bo);
                LDS32(bh[nt][1], wh + bo + 16);
            }
#pragma unroll
            for (int mt = 0; mt < 2; ++mt)
#pragma unroll
                for (int nt = 0; nt < 2; ++nt)
                    MMA_FP16(acc[mt][nt], ah[mt], bh[nt][0], bh[nt][1]);
        }
        if (c2 + 1 < NCHUNK2) storeXS(s ^ 1, nv);
        CP_ASYNC_WAIT0();
        __syncthreads();
    }

    // ---------- fused epilogue: transpose to smem rows, topk, histogram ----------
    float* rows = (float*)smem;               // [128][68] fp32
    int* c1s = (int*)(smem + 34816);          // [64]
    int* c2s = c1s + 64;                      // [64]

    {
        const int rr = warp_m * 32 + (lane >> 2);
        const int cc0 = warp_n * 16 + (lane & 3) * 2;
#pragma unroll
        for (int mt = 0; mt < 2; ++mt)
#pragma unroll
            for (int nt = 0; nt < 2; ++nt) {
                const int r = rr + mt * 16, cc = cc0 + nt * 8;
                rows[r * 68 + cc]           = acc[mt][nt][0];
                rows[r * 68 + cc + 1]       = acc[mt][nt][1];
                rows[(r + 8) * 68 + cc]     = acc[mt][nt][2];
                rows[(r + 8) * 68 + cc + 1] = acc[mt][nt][3];
            }
    }
    if (tid < 64) { c1s[tid] = 0; c2s[tid] = 0; }
    __syncthreads();

    // stream logits to gmem (for rescue): 2048 float4, 4 per thread
#pragma unroll
    for (int q = 0; q < 4; ++q) {
        const int idx = tid + q * 512;
        const int row = idx >> 4, col4 = idx & 15;
        const float* rp = rows + row * 68 + col4 * 4;
        *(float4*)&g_logits[(size_t)(m0 + row) * 64 + col4 * 4] =
            make_float4(rp[0], rp[1], rp[2], rp[3]);
    }

    // per-token topk (threads 0..127), identical arithmetic to prior topk256
    if (tid < 128) {
        const int i = m0 + tid;
        const float* L = rows + tid * 68;

        float v1 = -3.4e38f, v2 = -3.4e38f, v3 = -3.4e38f;
        int i1 = 0, i2 = 0;
#pragma unroll
        for (int q = 0; q < 16; ++q) {
#pragma unroll
            for (int r = 0; r < 4; ++r) {
                const float x = L[q * 4 + r]; const int idx = q * 4 + r;
                if (x > v1)      { v3 = v2; v2 = v1; i2 = i1; v1 = x; i1 = idx; }
                else if (x > v2) { v3 = v2; v2 = x; i2 = idx; }
                else if (x > v3) { v3 = x; }
            }
        }
        float s = 0.f;
#pragma unroll
        for (int q = 0; q < 16; ++q)
            s += ((expf(L[q * 4] - v1) + expf(L[q * 4 + 1] - v1)) + expf(L[q * 4 + 2] - v1)) + expf(L[q * 4 + 3] - v1);

        const float g1 = 1.0f / s;
        const float g2 = expf(v2 - v1) / s;
        const float denom = g1 + g2;
        const float g1n = g1 / denom, g2n = g2 / denom;
        const float rnd = jax_uniform_partitionable((uint32_t)i);
        const int want2 = (rnd < 2.0f * g2n) ? 1 : 0;

        g_e1[i] = i1; g_e2[i] = i2;
        g_g1n[i] = g1n; g_g2n[i] = g2n;
        g_want2[i] = want2;

        const float TAU_GAP = 2e-3f, TAU_RND = 1.2e-3f;
        if ((v1 - v2) < TAU_GAP || (v2 - v3) < TAU_GAP || fabsf(rnd - 2.0f * g2n) < TAU_RND) {
            const int k = atomicAdd(&g_nflag, 1);
            g_flagged[k] = i;
        }
        atomicAdd(&c1s[i1], 1);
        if (want2) atomicAdd(&c2s[i2], 1);
    }
    __syncthreads();
    if (tid < 64) {
        g_bc1T[tid * 128 + blockIdx.x] = c1s[tid];
        g_bc2T[tid * 128 + blockIdx.x] = c2s[tid];
    }
}

// ---------------- exact rescue: candidates-only, warp per flagged token ----------------
__global__ __launch_bounds__(256)
void rescue_exact(const float* __restrict__ X, const float* __restrict__ W) {
    const int warp = threadIdx.x >> 5, lane = threadIdx.x & 31;
    const int gwarp = blockIdx.x * 8 + warp;
    const int nwarps = gridDim.x * 8;
    const int nf = g_nflag;

    for (int fi = gwarp; fi < nf; fi += nwarps) {
        const int i = g_flagged[fi];
        const float* row = g_logits + (size_t)i * 64;
        const float l0 = row[lane];
        const float l1 = row[lane + 32];
        const float v2a = row[g_e2[i]];

        const float TAU_C = 2.5e-3f;
        const float thr = v2a - TAU_C;
        const unsigned mlo = __ballot_sync(0xffffffffu, l0 > thr);
        const unsigned mhi = __ballot_sync(0xffffffffu, l1 > thr);
        uint64_t cmask = ((uint64_t)mhi << 32) | (uint64_t)mlo;

        const float4* xr = (const float4*)(X + (size_t)i * D_DIM);

        float v1e = -3.4e38f, v2e = -3.4e38f;
        int i1e = 0, i2e = 0;
        while (cmask) {
            const int c = __ffsll((long long)cmask) - 1;
            cmask &= cmask - 1;
            const float4* wr = (const float4*)(W + (size_t)c * D_DIM);
            float a0 = 0.f, a1 = 0.f, a2 = 0.f, a3 = 0.f;
#pragma unroll
            for (int j = 0; j < 32; ++j) {
                const float4 xa = xr[j * 32 + lane];
                const float4 wa = wr[j * 32 + lane];
                a0 = fmaf(xa.x, wa.x, a0);
                a1 = fmaf(xa.y, wa.y, a1);
                a2 = fmaf(xa.z, wa.z, a2);
                a3 = fmaf(xa.w, wa.w, a3);
            }
            float tot = ((a0 + a1) + a2) + a3;
#pragma unroll
            for (int off = 16; off; off >>= 1)
                tot += __shfl_xor_sync(0xffffffffu, tot, off);
            if (tot > v1e)      { v2e = v1e; i2e = i1e; v1e = tot; i1e = c; }
            else if (tot > v2e) { v2e = tot; i2e = c; }
        }

        if (lane == 0) {
            const float t = expf(v2e - v1e);
            const float g1n = 1.0f / (1.0f + t);
            const float g2n = t / (1.0f + t);
            const float rnd = jax_uniform_partitionable((uint32_t)i);
            const int w2 = (rnd < 2.0f * g2n) ? 1 : 0;

            const int blkb = i >> 7;
            const int oe1 = g_e1[i], oe2 = g_e2[i], ow2 = g_want2[i];
            if (i1e != oe1) {
                atomicSub(&g_bc1T[oe1 * 128 + blkb], 1);
                atomicAdd(&g_bc1T[i1e * 128 + blkb], 1);
            }
            if (ow2) atomicSub(&g_bc2T[oe2 * 128 + blkb], 1);
            if (w2)  atomicAdd(&g_bc2T[i2e * 128 + blkb], 1);

            g_e1[i] = i1e;
            g_e2[i] = i2e;
            g_g1n[i] = g1n;
            g_g2n[i] = g2n;
            g_want2[i] = w2;
        }
    }
}

// ---------------- cross-block scan (transposed, int4, 128 blocks) ----------------
__global__ void scan_kernel() {
    const int e = threadIdx.x;
    if (e >= 64) return;
    int4 buf[32];
    const int4* s1 = (const int4*)(g_bc1T + e * 128);
#pragma unroll
    for (int q = 0; q < 32; ++q) buf[q] = s1[q];
    int r1 = 0;
#pragma unroll
    for (int q = 0; q < 32; ++q) {
        g_base1T[e * 128 + q * 4 + 0] = r1; r1 += buf[q].x;
        g_base1T[e * 128 + q * 4 + 1] = r1; r1 += buf[q].y;
        g_base1T[e * 128 + q * 4 + 2] = r1; r1 += buf[q].z;
        g_base1T[e * 128 + q * 4 + 3] = r1; r1 += buf[q].w;
    }
    const int4* s2 = (const int4*)(g_bc2T + e * 128);
#pragma unroll
    for (int q = 0; q < 32; ++q) buf[q] = s2[q];
    int r2 = 0;
#pragma unroll
    for (int q = 0; q < 32; ++q) {
        g_base2T[e * 128 + q * 4 + 0] = r2; r2 += buf[q].x;
        g_base2T[e * 128 + q * 4 + 1] = r2; r2 += buf[q].y;
        g_base2T[e * 128 + q * 4 + 2] = r2; r2 += buf[q].z;
        g_base2T[e * 128 + q * 4 + 3] = r2; r2 += buf[q].w;
    }
    g_cap2[e] = CAP - (r1 < CAP ? r1 : CAP);
}

// ---------------- final ranks + full-row write (128-token blocks) ----------------
__global__ __launch_bounds__(128)
void assign_kernel(float* __restrict__ out) {
    __shared__ int wc1[4][64];
    __shared__ int wc2[4][64];
    const int t = threadIdx.x, warp = t >> 5, lane = t & 31;
    const int blk = blockIdx.x;

    ((int*)wc1)[t] = 0; ((int*)wc1)[t + 128] = 0;
    ((int*)wc2)[t] = 0; ((int*)wc2)[t + 128] = 0;
    __syncthreads();

    const int i  = blk * 128 + t;
    const int e1 = g_e1[i], e2 = g_e2[i], want2 = g_want2[i];
    const unsigned lt = (1u << lane) - 1u;

    const unsigned m1 = __match_any_sync(0xffffffffu, e1);
    const int lr1 = __popc(m1 & lt);
    if (lr1 == 0) wc1[warp][e1] = __popc(m1);

    const unsigned act2 = __ballot_sync(0xffffffffu, want2);
    const unsigned m2 = __match_any_sync(0xffffffffu, e2) & act2;
    const int lr2 = __popc(m2 & lt);
    if (want2 && lr2 == 0) wc2[warp][e2] = __popc(m2);
    __syncthreads();

    int off1 = 0, off2 = 0;
    for (int w = 0; w < warp; ++w) {
        off1 += wc1[w][e1];
        off2 += wc2[w][e2];
    }

    const int pos1 = g_base1T[e1 * 128 + blk] + off1 + lr1 + 1;
    const int pos2 = g_base2T[e2 * 128 + blk] + off2 + lr2 + 1;
    const float val1 = (pos1 <= CAP) ? g_g1n[i] : 0.f;
    const float val2 = (want2 && pos2 <= g_cap2[e2]) ? g_g2n[i] : 0.f;

    float4* op = (float4*)(out + (size_t)i * 64);
#pragma unroll
    for (int q = 0; q < 16; ++q) {
        float4 z = make_float4(0.f, 0.f, 0.f, 0.f);
        if ((e1 >> 2) == q) ((float*)&z)[e1 & 3] = val1;
        if ((e2 >> 2) == q) ((float*)&z)[e2 & 3] = val2;
        op[q] = z;
    }
}

// ---------------- launcher ----------------
extern "C" void kernel_launch(void* const* d_in, const int* in_sizes, int n_in,
                              void* d_out, int out_size) {
    const float* x = (const float*)d_in[0];
    const float* w = (const float*)d_in[1];
    float* out = (float*)d_out;

    cudaFuncSetAttribute(gemm_fused, cudaFuncAttributeMaxDynamicSharedMemorySize, GEMM_SMEM);

    wconv_kernel<<<512, 256>>>(w);
    gemm_fused<<<S_TOK / BM, 512, GEMM_SMEM>>>(x);
    rescue_exact<<<256, 256>>>(x, w);
    scan_kernel<<<1, 64>>>();
    assign_kernel<<<S_TOK / 128, 128>>>(out);
}

// round 13
// speedup vs baseline: 1.6843x; 1.1062x over previous
#include <cuda_runtime.h>
#include <cuda_fp16.h>
#include <cstdint>

#define S_TOK 16384
#define D_DIM 4096
#define N_EXP 64
#define CAP   320
#define NCHUNK2 32               // outer iterations, 128 K-elems each
#define BM    128

#define SWZ(o) ((o) ^ (((o) >> 3) & 0x70))

// ---------------- scratch ----------------
__device__ float g_logits[S_TOK * N_EXP];
__device__ __align__(16) uint32_t g_whT[64 * 2304];
__device__ int   g_e1[S_TOK];
__device__ int   g_e2[S_TOK];
__device__ int   g_want2[S_TOK];
__device__ float g_g1n[S_TOK];
__device__ float g_g2n[S_TOK];
__device__ int   g_bc1T[64 * 128];   // [expert][128-token block]
__device__ int   g_bc2T[64 * 128];
__device__ int   g_base1T[64 * 128];
__device__ int   g_base2T[64 * 128];
__device__ int   g_cap2[64];
__device__ int   g_nflag;
__device__ int   g_flagged[S_TOK];

// ---------------- PTX helpers ----------------
__device__ __forceinline__ uint32_t smem_to_u32(const void* p) {
    uint32_t a;
    asm("{ .reg .u64 t; cvta.to.shared.u64 t, %1; cvt.u32.u64 %0, t; }" : "=r"(a) : "l"(p));
    return a;
}
#define CP_ASYNC16(dst, src) \
    asm volatile("cp.async.cg.shared.global [%0], [%1], 16;" :: "r"(dst), "l"(src) : "memory")
#define CP_ASYNC_COMMIT()  asm volatile("cp.async.commit_group;" ::: "memory")
#define CP_ASYNC_WAIT0()   asm volatile("cp.async.wait_group 0;" ::: "memory")

#define LDSM_X4(r0, r1, r2, r3, addr) \
    asm volatile("ldmatrix.sync.aligned.m8n8.x4.shared.b16 {%0,%1,%2,%3}, [%4];" \
        : "=r"(r0), "=r"(r1), "=r"(r2), "=r"(r3) : "r"(addr))

#define LDS32(r, addr) \
    asm volatile("ld.shared.b32 %0, [%1];" : "=r"(r) : "r"(addr))

#define MMA_FP16(d, a, b0, b1) \
    asm volatile("mma.sync.aligned.m16n8k16.row.col.f32.f16.f16.f32 " \
        "{%0,%1,%2,%3}, {%4,%5,%6,%7}, {%8,%9}, {%0,%1,%2,%3};" \
        : "+f"((d)[0]), "+f"((d)[1]), "+f"((d)[2]), "+f"((d)[3]) \
        : "r"((a)[0]), "r"((a)[1]), "r"((a)[2]), "r"((a)[3]), "r"(b0), "r"(b1))

// gemm smem layout: XS stage = 2 sub-tiles of 16KB; WHS stage = 2 sub-tiles of 9216B
#define XS(s)  (sb + (s) * 32768)
#define WHS(s) (sb + 65536 + (s) * 18432)
#define GEMM_SMEM 102400

// ---------------- Threefry-2x32 (JAX partitionable, key(1)) ----------------
__device__ __forceinline__ void threefry2x32(uint32_t x0, uint32_t x1,
                                             uint32_t& o0, uint32_t& o1) {
    const uint32_t k0 = 0u, k1 = 1u, k2 = 0x1BD11BDBu;
    x0 += k0; x1 += k1;
#define TFR(r) { x0 += x1; x1 = (x1 << (r)) | (x1 >> (32 - (r))); x1 ^= x0; }
    TFR(13) TFR(15) TFR(26) TFR(6)  x0 += k1; x1 += k2 + 1u;
    TFR(17) TFR(29) TFR(16) TFR(24) x0 += k2; x1 += k0 + 2u;
    TFR(13) TFR(15) TFR(26) TFR(6)  x0 += k0; x1 += k1 + 3u;
    TFR(17) TFR(29) TFR(16) TFR(24) x0 += k1; x1 += k2 + 4u;
    TFR(13) TFR(15) TFR(26) TFR(6)  x0 += k2; x1 += k0 + 5u;
#undef TFR
    o0 = x0; o1 = x1;
}
__device__ __forceinline__ float jax_uniform_partitionable(uint32_t i) {
    uint32_t o0, o1;
    threefry2x32(0u, i, o0, o1);
    const uint32_t bits = o0 ^ o1;
    return __uint_as_float((bits >> 9) | 0x3f800000u) - 1.0f;
}

// ---------------- W pre-conversion (also resets flag counter) ----------------
__global__ __launch_bounds__(256)
void wconv_kernel(const float* __restrict__ W) {
    const int pid = blockIdx.x * 256 + threadIdx.x;   // 0..131071
    if (pid == 0) g_nflag = 0;
    const int n = pid >> 11;                          // expert 0..63
    const int j = pid & 2047;                         // k-pair 0..2047
    const float2 v = *(const float2*)(W + (size_t)n * D_DIM + j * 2);
    const __half h0 = __float2half_rn(v.x);
    const __half h1 = __float2half_rn(v.y);
    const uint32_t hp = (uint32_t)__half_as_ushort(h0) | ((uint32_t)__half_as_ushort(h1) << 16);
    g_whT[(j >> 5) * 2304 + n * 36 + (j & 31)] = hp;
}

// ---------------- fused GEMM + topk/softmax/want2/flag/histogram ----------------
__global__ __launch_bounds__(512, 1)
void gemm_fused(const float* __restrict__ X) {
    extern __shared__ __align__(1024) char smem[];
    const uint32_t sb = smem_to_u32(smem);
    const int tid = threadIdx.x, wid = tid >> 5, lane = tid & 31;
    const int m0 = blockIdx.x * BM;
    const int warp_m = wid & 3, warp_n = wid >> 2;   // 4M x 4N, warp tile m32 x n16

    float acc[2][2][4];
#pragma unroll
    for (int a = 0; a < 2; ++a)
#pragma unroll
        for (int b = 0; b < 2; ++b)
#pragma unroll
            for (int q = 0; q < 4; ++q) acc[a][b][q] = 0.f;

    const int xrow = tid >> 2, xc4 = tid & 3;
    const float4* xp = (const float4*)(X + (size_t)(m0 + xrow) * D_DIM);

    const uint32_t a_b0  = (uint32_t)((warp_m * 32 + (lane & 15)) * 128 + (lane >> 4) * 16);
    const uint32_t b_off = (uint32_t)((warp_n * 16 + (lane >> 2)) * 144 + (lane & 3) * 4);

    auto loadB = [&](int c2, int s) {
        const char* g0 = (const char*)(g_whT + (2 * c2) * 2304);
        const char* g1 = (const char*)(g_whT + (2 * c2 + 1) * 2304);
        const uint32_t wh = WHS(s);
        CP_ASYNC16(wh + tid * 16, g0 + tid * 16);
        CP_ASYNC16(wh + 9216 + tid * 16, g1 + tid * 16);
        if (tid < 64) {
            CP_ASYNC16(wh + (512 + tid) * 16, g0 + (512 + tid) * 16);
            CP_ASYNC16(wh + 9216 + (512 + tid) * 16, g1 + (512 + tid) * 16);
        }
    };
    auto loadx = [&](int c2, float4* v) {
#pragma unroll
        for (int it = 0; it < 8; ++it)
            v[it] = xp[c2 * 32 + xc4 + it * 4];
    };
    auto storeXS = [&](int s, const float4* v) {
        const uint32_t xs = XS(s);
#pragma unroll
        for (int it = 0; it < 8; ++it) {
            const __half2 h01 = __floats2half2_rn(v[it].x, v[it].y);
            const __half2 h23 = __floats2half2_rn(v[it].z, v[it].w);
            const uint32_t p0 = *(const uint32_t*)&h01;
            const uint32_t p1 = *(const uint32_t*)&h23;
            const int col4 = xc4 + it * 4;               // 0..31 within 128-col pair
            const int sub = col4 >> 4;
            const uint32_t off = (uint32_t)(sub * 16384) +
                                 SWZ((uint32_t)(xrow * 128 + (col4 & 15) * 8));
            asm volatile("st.shared.v2.b32 [%0], {%1,%2};" :: "r"(xs + off), "r"(p0), "r"(p1) : "memory");
        }
    };

    // prologue
    float4 v[8];
    loadB(0, 0);
    CP_ASYNC_COMMIT();
    loadx(0, v);
    storeXS(0, v);
    CP_ASYNC_WAIT0();
    __syncthreads();

    for (int c2 = 0; c2 < NCHUNK2; ++c2) {
        const int s = c2 & 1;
        float4 nv[8];
        if (c2 + 1 < NCHUNK2) {
            loadB(c2 + 1, s ^ 1);
            CP_ASYNC_COMMIT();
            loadx(c2 + 1, nv);
        }
#pragma unroll
        for (int ks = 0; ks < 8; ++ks) {
            const int sub = ks >> 2, ksl = ks & 3;
            const uint32_t xs = XS(s) + sub * 16384;
            const uint32_t wh = WHS(s) + sub * 9216;
            uint32_t ah[2][4];
            LDSM_X4(ah[0][0], ah[0][1], ah[0][2], ah[0][3], xs + SWZ(a_b0 + ksl * 32));
            LDSM_X4(ah[1][0], ah[1][1], ah[1][2], ah[1][3], xs + SWZ(a_b0 + 2048 + ksl * 32));
            uint32_t bh[2][2];
#pragma unroll
            for (int nt = 0; nt < 2; ++nt) {
                const uint32_t bo = b_off + nt * 1152 + ksl * 32;
                LDS32(bh[nt][0], wh + bo);
                LDS32(bh[nt][1], wh + bo + 16);
            }
#pragma unroll
            for (int mt = 0; mt < 2; ++mt)
#pragma unroll
                for (int nt = 0; nt < 2; ++nt)
                    MMA_FP16(acc[mt][nt], ah[mt], bh[nt][0], bh[nt][1]);
        }
        if (c2 + 1 < NCHUNK2) storeXS(s ^ 1, nv);
        CP_ASYNC_WAIT0();
        __syncthreads();
    }

    // ---------- fused epilogue: transpose to smem rows, topk, histogram ----------
    float* rows = (float*)smem;               // [128][68] fp32
    int* c1s = (int*)(smem + 34816);          // [64]
    int* c2s = c1s + 64;                      // [64]

    {
        const int rr = warp_m * 32 + (lane >> 2);
        const int cc0 = warp_n * 16 + (lane & 3) * 2;
#pragma unroll
        for (int mt = 0; mt < 2; ++mt)
#pragma unroll
            for (int nt = 0; nt < 2; ++nt) {
                const int r = rr + mt * 16, cc = cc0 + nt * 8;
                rows[r * 68 + cc]           = acc[mt][nt][0];
                rows[r * 68 + cc + 1]       = acc[mt][nt][1];
                rows[(r + 8) * 68 + cc]     = acc[mt][nt][2];
                rows[(r + 8) * 68 + cc + 1] = acc[mt][nt][3];
            }
    }
    if (tid < 64) { c1s[tid] = 0; c2s[tid] = 0; }
    __syncthreads();

    // stream logits to gmem (for rescue): 2048 float4, 4 per thread
#pragma unroll
    for (int q = 0; q < 4; ++q) {
        const int idx = tid + q * 512;
        const int row = idx >> 4, col4 = idx & 15;
        const float* rp = rows + row * 68 + col4 * 4;
        *(float4*)&g_logits[(size_t)(m0 + row) * 64 + col4 * 4] =
            make_float4(rp[0], rp[1], rp[2], rp[3]);
    }

    // per-token topk (threads 0..127), identical arithmetic to prior topk256
    if (tid < 128) {
        const int i = m0 + tid;
        const float* L = rows + tid * 68;

        float v1 = -3.4e38f, v2 = -3.4e38f, v3 = -3.4e38f;
        int i1 = 0, i2 = 0;
#pragma unroll
        for (int q = 0; q < 16; ++q) {
#pragma unroll
            for (int r = 0; r < 4; ++r) {
                const float x = L[q * 4 + r]; const int idx = q * 4 + r;
                if (x > v1)      { v3 = v2; v2 = v1; i2 = i1; v1 = x; i1 = idx; }
                else if (x > v2) { v3 = v2; v2 = x; i2 = idx; }
                else if (x > v3) { v3 = x; }
            }
        }
        float s = 0.f;
#pragma unroll
        for (int q = 0; q < 16; ++q)
            s += ((expf(L[q * 4] - v1) + expf(L[q * 4 + 1] - v1)) + expf(L[q * 4 + 2] - v1)) + expf(L[q * 4 + 3] - v1);

        const float g1 = 1.0f / s;
        const float g2 = expf(v2 - v1) / s;
        const float denom = g1 + g2;
        const float g1n = g1 / denom, g2n = g2 / denom;
        const float rnd = jax_uniform_partitionable((uint32_t)i);
        const int want2 = (rnd < 2.0f * g2n) ? 1 : 0;

        g_e1[i] = i1; g_e2[i] = i2;
        g_g1n[i] = g1n; g_g2n[i] = g2n;
        g_want2[i] = want2;

        const float TAU_GAP = 2e-3f, TAU_RND = 1.2e-3f;
        if ((v1 - v2) < TAU_GAP || (v2 - v3) < TAU_GAP || fabsf(rnd - 2.0f * g2n) < TAU_RND) {
            const int k = atomicAdd(&g_nflag, 1);
            g_flagged[k] = i;
        }
        atomicAdd(&c1s[i1], 1);
        if (want2) atomicAdd(&c2s[i2], 1);
    }
    __syncthreads();
    if (tid < 64) {
        g_bc1T[tid * 128 + blockIdx.x] = c1s[tid];
        g_bc2T[tid * 128 + blockIdx.x] = c2s[tid];
    }
}

// ---------------- exact rescue: candidates-only, warp per flagged token ----------------
__global__ __launch_bounds__(256)
void rescue_exact(const float* __restrict__ X, const float* __restrict__ W) {
    const int warp = threadIdx.x >> 5, lane = threadIdx.x & 31;
    const int gwarp = blockIdx.x * 8 + warp;
    const int nwarps = gridDim.x * 8;
    const int nf = g_nflag;

    for (int fi = gwarp; fi < nf; fi += nwarps) {
        const int i = g_flagged[fi];
        const float* row = g_logits + (size_t)i * 64;
        const float l0 = row[lane];
        const float l1 = row[lane + 32];
        const float v2a = row[g_e2[i]];

        const float TAU_C = 2.5e-3f;
        const float thr = v2a - TAU_C;
        const unsigned mlo = __ballot_sync(0xffffffffu, l0 > thr);
        const unsigned mhi = __ballot_sync(0xffffffffu, l1 > thr);
        uint64_t cmask = ((uint64_t)mhi << 32) | (uint64_t)mlo;

        const float4* xr = (const float4*)(X + (size_t)i * D_DIM);

        float v1e = -3.4e38f, v2e = -3.4e38f;
        int i1e = 0, i2e = 0;
        while (cmask) {
            const int c = __ffsll((long long)cmask) - 1;
            cmask &= cmask - 1;
            const float4* wr = (const float4*)(W + (size_t)c * D_DIM);
            float a0 = 0.f, a1 = 0.f, a2 = 0.f, a3 = 0.f;
#pragma unroll
            for (int j = 0; j < 32; ++j) {
                const float4 xa = xr[j * 32 + lane];
                const float4 wa = wr[j * 32 + lane];
                a0 = fmaf(xa.x, wa.x, a0);
                a1 = fmaf(xa.y, wa.y, a1);
                a2 = fmaf(xa.z, wa.z, a2);
                a3 = fmaf(xa.w, wa.w, a3);
            }
            float tot = ((a0 + a1) + a2) + a3;
#pragma unroll
            for (int off = 16; off; off >>= 1)
                tot += __shfl_xor_sync(0xffffffffu, tot, off);
            if (tot > v1e)      { v2e = v1e; i2e = i1e; v1e = tot; i1e = c; }
            else if (tot > v2e) { v2e = tot; i2e = c; }
        }

        if (lane == 0) {
            const float t = expf(v2e - v1e);
            const float g1n = 1.0f / (1.0f + t);
            const float g2n = t / (1.0f + t);
            const float rnd = jax_uniform_partitionable((uint32_t)i);
            const int w2 = (rnd < 2.0f * g2n) ? 1 : 0;

            const int blkb = i >> 7;
            const int oe1 = g_e1[i], oe2 = g_e2[i], ow2 = g_want2[i];
            if (i1e != oe1) {
                atomicSub(&g_bc1T[oe1 * 128 + blkb], 1);
                atomicAdd(&g_bc1T[i1e * 128 + blkb], 1);
            }
            if (ow2) atomicSub(&g_bc2T[oe2 * 128 + blkb], 1);
            if (w2)  atomicAdd(&g_bc2T[i2e * 128 + blkb], 1);

            g_e1[i] = i1e;
            g_e2[i] = i2e;
            g_g1n[i] = g1n;
            g_g2n[i] = g2n;
            g_want2[i] = w2;
        }
    }
}

// ---------------- parallel cross-block scan: 32 warps, 2 experts each ----------------
__global__ __launch_bounds__(1024)
void scan_kernel() {
    const int warp = threadIdx.x >> 5, lane = threadIdx.x & 31;

#pragma unroll
    for (int half = 0; half < 2; ++half) {
        const int e = warp + half * 32;

        // ---- pass 1 (bc1) ----
        {
            const int4 v = ((const int4*)(g_bc1T + e * 128))[lane];
            const int s = v.x + v.y + v.z + v.w;
            int pre = s;
#pragma unroll
            for (int off = 1; off < 32; off <<= 1) {
                const int n = __shfl_up_sync(0xffffffffu, pre, off);
                if (lane >= off) pre += n;
            }
            int excl = pre - s;
            int4 b;
            b.x = excl; excl += v.x;
            b.y = excl; excl += v.y;
            b.z = excl; excl += v.z;
            b.w = excl;
            ((int4*)(g_base1T + e * 128))[lane] = b;
            const int r1 = __shfl_sync(0xffffffffu, pre, 31);
            if (lane == 0) g_cap2[e] = CAP - (r1 < CAP ? r1 : CAP);
        }
        // ---- pass 2 (bc2) ----
        {
            const int4 v = ((const int4*)(g_bc2T + e * 128))[lane];
            const int s = v.x + v.y + v.z + v.w;
            int pre = s;
#pragma unroll
            for (int off = 1; off < 32; off <<= 1) {
                const int n = __shfl_up_sync(0xffffffffu, pre, off);
                if (lane >= off) pre += n;
            }
            int excl = pre - s;
            int4 b;
            b.x = excl; excl += v.x;
            b.y = excl; excl += v.y;
            b.z = excl; excl += v.z;
            b.w = excl;
            ((int4*)(g_base2T + e * 128))[lane] = b;
        }
    }
}

// ---------------- final ranks + full-row write (128-token blocks) ----------------
__global__ __launch_bounds__(128)
void assign_kernel(float* __restrict__ out) {
    __shared__ int wc1[4][64];
    __shared__ int wc2[4][64];
    const int t = threadIdx.x, warp = t >> 5, lane = t & 31;
    const int blk = blockIdx.x;

    ((int*)wc1)[t] = 0; ((int*)wc1)[t + 128] = 0;
    ((int*)wc2)[t] = 0; ((int*)wc2)[t + 128] = 0;
    __syncthreads();

    const int i  = blk * 128 + t;
    const int e1 = g_e1[i], e2 = g_e2[i], want2 = g_want2[i];
    const unsigned lt = (1u << lane) - 1u;

    const unsigned m1 = __match_any_sync(0xffffffffu, e1);
    const int lr1 = __popc(m1 & lt);
    if (lr1 == 0) wc1[warp][e1] = __popc(m1);

    const unsigned act2 = __ballot_sync(0xffffffffu, want2);
    const unsigned m2 = __match_any_sync(0xffffffffu, e2) & act2;
    const int lr2 = __popc(m2 & lt);
    if (want2 && lr2 == 0) wc2[warp][e2] = __popc(m2);
    __syncthreads();

    int off1 = 0, off2 = 0;
    for (int w = 0; w < warp; ++w) {
        off1 += wc1[w][e1];
        off2 += wc2[w][e2];
    }

    const int pos1 = g_base1T[e1 * 128 + blk] + off1 + lr1 + 1;
    const int pos2 = g_base2T[e2 * 128 + blk] + off2 + lr2 + 1;
    const float val1 = (pos1 <= CAP) ? g_g1n[i] : 0.f;
    const float val2 = (want2 && pos2 <= g_cap2[e2]) ? g_g2n[i] : 0.f;

    float4* op = (float4*)(out + (size_t)i * 64);
#pragma unroll
    for (int q = 0; q < 16; ++q) {
        float4 z = make_float4(0.f, 0.f, 0.f, 0.f);
        if ((e1 >> 2) == q) ((float*)&z)[e1 & 3] = val1;
        if ((e2 >> 2) == q) ((float*)&z)[e2 & 3] = val2;
        op[q] = z;
    }
}

// ---------------- launcher ----------------
extern "C" void kernel_launch(void* const* d_in, const int* in_sizes, int n_in,
                              void* d_out, int out_size) {
    const float* x = (const float*)d_in[0];
    const float* w = (const float*)d_in[1];
    float* out = (float*)d_out;

    cudaFuncSetAttribute(gemm_fused, cudaFuncAttributeMaxDynamicSharedMemorySize, GEMM_SMEM);

    wconv_kernel<<<512, 256>>>(w);
    gemm_fused<<<S_TOK / BM, 512, GEMM_SMEM>>>(x);
    rescue_exact<<<256, 256>>>(x, w);
    scan_kernel<<<1, 1024>>>();
    assign_kernel<<<S_TOK / 128, 128>>>(out);
}

// round 14
// speedup vs baseline: 1.7325x; 1.0286x over previous
#include <cuda_runtime.h>
#include <cuda_fp16.h>
#include <cstdint>

#define S_TOK 16384
#define D_DIM 4096
#define N_EXP 64
#define CAP   320
#define NCHUNK2 32               // outer iterations, 128 K-elems each
#define BM    128

#define SWZ(o) ((o) ^ (((o) >> 3) & 0x70))

// ---------------- scratch ----------------
__device__ float g_logits[S_TOK * N_EXP];
__device__ __align__(16) uint32_t g_whT[64 * 2304];
__device__ int   g_e1[S_TOK];
__device__ int   g_e2[S_TOK];
__device__ int   g_want2[S_TOK];
__device__ float g_g1n[S_TOK];
__device__ float g_g2n[S_TOK];
__device__ int   g_bc1T[64 * 128];   // [expert][128-token block]
__device__ int   g_bc2T[64 * 128];
__device__ int   g_nflag;
__device__ int   g_flagged[S_TOK];

// ---------------- PTX helpers ----------------
__device__ __forceinline__ uint32_t smem_to_u32(const void* p) {
    uint32_t a;
    asm("{ .reg .u64 t; cvta.to.shared.u64 t, %1; cvt.u32.u64 %0, t; }" : "=r"(a) : "l"(p));
    return a;
}
#define CP_ASYNC16(dst, src) \
    asm volatile("cp.async.cg.shared.global [%0], [%1], 16;" :: "r"(dst), "l"(src) : "memory")
#define CP_ASYNC_COMMIT()  asm volatile("cp.async.commit_group;" ::: "memory")
#define CP_ASYNC_WAIT0()   asm volatile("cp.async.wait_group 0;" ::: "memory")

#define LDSM_X4(r0, r1, r2, r3, addr) \
    asm volatile("ldmatrix.sync.aligned.m8n8.x4.shared.b16 {%0,%1,%2,%3}, [%4];" \
        : "=r"(r0), "=r"(r1), "=r"(r2), "=r"(r3) : "r"(addr))

#define LDS32(r, addr) \
    asm volatile("ld.shared.b32 %0, [%1];" : "=r"(r) : "r"(addr))

#define MMA_FP16(d, a, b0, b1) \
    asm volatile("mma.sync.aligned.m16n8k16.row.col.f32.f16.f16.f32 " \
        "{%0,%1,%2,%3}, {%4,%5,%6,%7}, {%8,%9}, {%0,%1,%2,%3};" \
        : "+f"((d)[0]), "+f"((d)[1]), "+f"((d)[2]), "+f"((d)[3]) \
        : "r"((a)[0]), "r"((a)[1]), "r"((a)[2]), "r"((a)[3]), "r"(b0), "r"(b1))

// gemm smem layout: XS stage = 2 sub-tiles of 16KB; WHS stage = 2 sub-tiles of 9216B
#define XS(s)  (sb + (s) * 32768)
#define WHS(s) (sb + 65536 + (s) * 18432)
#define GEMM_SMEM 102400

// ---------------- Threefry-2x32 (JAX partitionable, key(1)) ----------------
__device__ __forceinline__ void threefry2x32(uint32_t x0, uint32_t x1,
                                             uint32_t& o0, uint32_t& o1) {
    const uint32_t k0 = 0u, k1 = 1u, k2 = 0x1BD11BDBu;
    x0 += k0; x1 += k1;
#define TFR(r) { x0 += x1; x1 = (x1 << (r)) | (x1 >> (32 - (r))); x1 ^= x0; }
    TFR(13) TFR(15) TFR(26) TFR(6)  x0 += k1; x1 += k2 + 1u;
    TFR(17) TFR(29) TFR(16) TFR(24) x0 += k2; x1 += k0 + 2u;
    TFR(13) TFR(15) TFR(26) TFR(6)  x0 += k0; x1 += k1 + 3u;
    TFR(17) TFR(29) TFR(16) TFR(24) x0 += k1; x1 += k2 + 4u;
    TFR(13) TFR(15) TFR(26) TFR(6)  x0 += k2; x1 += k0 + 5u;
#undef TFR
    o0 = x0; o1 = x1;
}
__device__ __forceinline__ float jax_uniform_partitionable(uint32_t i) {
    uint32_t o0, o1;
    threefry2x32(0u, i, o0, o1);
    const uint32_t bits = o0 ^ o1;
    return __uint_as_float((bits >> 9) | 0x3f800000u) - 1.0f;
}

// ---------------- W pre-conversion (also resets flag counter) ----------------
__global__ __launch_bounds__(256)
void wconv_kernel(const float* __restrict__ W) {
    const int pid = blockIdx.x * 256 + threadIdx.x;   // 0..131071
    if (pid == 0) g_nflag = 0;
    const int n = pid >> 11;                          // expert 0..63
    const int j = pid & 2047;                         // k-pair 0..2047
    const float2 v = *(const float2*)(W + (size_t)n * D_DIM + j * 2);
    const __half h0 = __float2half_rn(v.x);
    const __half h1 = __float2half_rn(v.y);
    const uint32_t hp = (uint32_t)__half_as_ushort(h0) | ((uint32_t)__half_as_ushort(h1) << 16);
    g_whT[(j >> 5) * 2304 + n * 36 + (j & 31)] = hp;
}

// ---------------- fused GEMM + topk/softmax/want2/flag/histogram ----------------
__global__ __launch_bounds__(512, 1)
void gemm_fused(const float* __restrict__ X) {
    extern __shared__ __align__(1024) char smem[];
    const uint32_t sb = smem_to_u32(smem);
    const int tid = threadIdx.x, wid = tid >> 5, lane = tid & 31;
    const int m0 = blockIdx.x * BM;
    const int warp_m = wid & 3, warp_n = wid >> 2;   // 4M x 4N, warp tile m32 x n16

    float acc[2][2][4];
#pragma unroll
    for (int a = 0; a < 2; ++a)
#pragma unroll
        for (int b = 0; b < 2; ++b)
#pragma unroll
            for (int q = 0; q < 4; ++q) acc[a][b][q] = 0.f;

    const int xrow = tid >> 2, xc4 = tid & 3;
    const float4* xp = (const float4*)(X + (size_t)(m0 + xrow) * D_DIM);

    const uint32_t a_b0  = (uint32_t)((warp_m * 32 + (lane & 15)) * 128 + (lane >> 4) * 16);
    const uint32_t b_off = (uint32_t)((warp_n * 16 + (lane >> 2)) * 144 + (lane & 3) * 4);

    auto loadB = [&](int c2, int s) {
        const char* g0 = (const char*)(g_whT + (2 * c2) * 2304);
        const char* g1 = (const char*)(g_whT + (2 * c2 + 1) * 2304);
        const uint32_t wh = WHS(s);
        CP_ASYNC16(wh + tid * 16, g0 + tid * 16);
        CP_ASYNC16(wh + 9216 + tid * 16, g1 + tid * 16);
        if (tid < 64) {
            CP_ASYNC16(wh + (512 + tid) * 16, g0 + (512 + tid) * 16);
            CP_ASYNC16(wh + 9216 + (512 + tid) * 16, g1 + (512 + tid) * 16);
        }
    };
    auto loadx = [&](int c2, float4* v) {
#pragma unroll
        for (int it = 0; it < 8; ++it)
            v[it] = xp[c2 * 32 + xc4 + it * 4];
    };
    auto storeXS = [&](int s, const float4* v) {
        const uint32_t xs = XS(s);
#pragma unroll
        for (int it = 0; it < 8; ++it) {
            const __half2 h01 = __floats2half2_rn(v[it].x, v[it].y);
            const __half2 h23 = __floats2half2_rn(v[it].z, v[it].w);
            const uint32_t p0 = *(const uint32_t*)&h01;
            const uint32_t p1 = *(const uint32_t*)&h23;
            const int col4 = xc4 + it * 4;               // 0..31 within 128-col pair
            const int sub = col4 >> 4;
            const uint32_t off = (uint32_t)(sub * 16384) +
                                 SWZ((uint32_t)(xrow * 128 + (col4 & 15) * 8));
            asm volatile("st.shared.v2.b32 [%0], {%1,%2};" :: "r"(xs + off), "r"(p0), "r"(p1) : "memory");
        }
    };

    // prologue
    float4 v[8];
    loadB(0, 0);
    CP_ASYNC_COMMIT();
    loadx(0, v);
    storeXS(0, v);
    CP_ASYNC_WAIT0();
    __syncthreads();

    for (int c2 = 0; c2 < NCHUNK2; ++c2) {
        const int s = c2 & 1;
        float4 nv[8];
        if (c2 + 1 < NCHUNK2) {
            loadB(c2 + 1, s ^ 1);
            CP_ASYNC_COMMIT();
            loadx(c2 + 1, nv);
        }
#pragma unroll
        for (int ks = 0; ks < 8; ++ks) {
            const int sub = ks >> 2, ksl = ks & 3;
            const uint32_t xs = XS(s) + sub * 16384;
            const uint32_t wh = WHS(s) + sub * 9216;
            uint32_t ah[2][4];
            LDSM_X4(ah[0][0], ah[0][1], ah[0][2], ah[0][3], xs + SWZ(a_b0 + ksl * 32));
            LDSM_X4(ah[1][0], ah[1][1], ah[1][2], ah[1][3], xs + SWZ(a_b0 + 2048 + ksl * 32));
            uint32_t bh[2][2];
#pragma unroll
            for (int nt = 0; nt < 2; ++nt) {
                const uint32_t bo = b_off + nt * 1152 + ksl * 32;
                LDS32(bh[nt][0], wh + bo);
                LDS32(bh[nt][1], wh + bo + 16);
            }
#pragma unroll
            for (int mt = 0; mt < 2; ++mt)
#pragma unroll
                for (int nt = 0; nt < 2; ++nt)
                    MMA_FP16(acc[mt][nt], ah[mt], bh[nt][0], bh[nt][1]);
        }
        if (c2 + 1 < NCHUNK2) storeXS(s ^ 1, nv);
        CP_ASYNC_WAIT0();
        __syncthreads();
    }

    // ---------- fused epilogue: transpose to smem rows, topk, histogram ----------
    float* rows = (float*)smem;               // [128][68] fp32
    int* c1s = (int*)(smem + 34816);          // [64]
    int* c2s = c1s + 64;                      // [64]

    {
        const int rr = warp_m * 32 + (lane >> 2);
        const int cc0 = warp_n * 16 + (lane & 3) * 2;
#pragma unroll
        for (int mt = 0; mt < 2; ++mt)
#pragma unroll
            for (int nt = 0; nt < 2; ++nt) {
                const int r = rr + mt * 16, cc = cc0 + nt * 8;
                rows[r * 68 + cc]           = acc[mt][nt][0];
                rows[r * 68 + cc + 1]       = acc[mt][nt][1];
                rows[(r + 8) * 68 + cc]     = acc[mt][nt][2];
                rows[(r + 8) * 68 + cc + 1] = acc[mt][nt][3];
            }
    }
    if (tid < 64) { c1s[tid] = 0; c2s[tid] = 0; }
    __syncthreads();

    // stream logits to gmem (for rescue): 2048 float4, 4 per thread
#pragma unroll
    for (int q = 0; q < 4; ++q) {
        const int idx = tid + q * 512;
        const int row = idx >> 4, col4 = idx & 15;
        const float* rp = rows + row * 68 + col4 * 4;
        *(float4*)&g_logits[(size_t)(m0 + row) * 64 + col4 * 4] =
            make_float4(rp[0], rp[1], rp[2], rp[3]);
    }

    // per-token topk (threads 0..127), identical arithmetic to prior topk256
    if (tid < 128) {
        const int i = m0 + tid;
        const float* L = rows + tid * 68;

        float v1 = -3.4e38f, v2 = -3.4e38f, v3 = -3.4e38f;
        int i1 = 0, i2 = 0;
#pragma unroll
        for (int q = 0; q < 16; ++q) {
#pragma unroll
            for (int r = 0; r < 4; ++r) {
                const float x = L[q * 4 + r]; const int idx = q * 4 + r;
                if (x > v1)      { v3 = v2; v2 = v1; i2 = i1; v1 = x; i1 = idx; }
                else if (x > v2) { v3 = v2; v2 = x; i2 = idx; }
                else if (x > v3) { v3 = x; }
            }
        }
        float s = 0.f;
#pragma unroll
        for (int q = 0; q < 16; ++q)
            s += ((expf(L[q * 4] - v1) + expf(L[q * 4 + 1] - v1)) + expf(L[q * 4 + 2] - v1)) + expf(L[q * 4 + 3] - v1);

        const float g1 = 1.0f / s;
        const float g2 = expf(v2 - v1) / s;
        const float denom = g1 + g2;
        const float g1n = g1 / denom, g2n = g2 / denom;
        const float rnd = jax_uniform_partitionable((uint32_t)i);
        const int want2 = (rnd < 2.0f * g2n) ? 1 : 0;

        g_e1[i] = i1; g_e2[i] = i2;
        g_g1n[i] = g1n; g_g2n[i] = g2n;
        g_want2[i] = want2;

        const float TAU_GAP = 2e-3f, TAU_RND = 1.2e-3f;
        if ((v1 - v2) < TAU_GAP || (v2 - v3) < TAU_GAP || fabsf(rnd - 2.0f * g2n) < TAU_RND) {
            const int k = atomicAdd(&g_nflag, 1);
            g_flagged[k] = i;
        }
        atomicAdd(&c1s[i1], 1);
        if (want2) atomicAdd(&c2s[i2], 1);
    }
    __syncthreads();
    if (tid < 64) {
        g_bc1T[tid * 128 + blockIdx.x] = c1s[tid];
        g_bc2T[tid * 128 + blockIdx.x] = c2s[tid];
    }
}

// ---------------- exact rescue: candidates-only, warp per flagged token ----------------
__global__ __launch_bounds__(256)
void rescue_exact(const float* __restrict__ X, const float* __restrict__ W) {
    const int warp = threadIdx.x >> 5, lane = threadIdx.x & 31;
    const int gwarp = blockIdx.x * 8 + warp;
    const int nwarps = gridDim.x * 8;
    const int nf = g_nflag;

    for (int fi = gwarp; fi < nf; fi += nwarps) {
        const int i = g_flagged[fi];
        const float* row = g_logits + (size_t)i * 64;
        const float l0 = row[lane];
        const float l1 = row[lane + 32];
        const float v2a = row[g_e2[i]];

        const float TAU_C = 2.5e-3f;
        const float thr = v2a - TAU_C;
        const unsigned mlo = __ballot_sync(0xffffffffu, l0 > thr);
        const unsigned mhi = __ballot_sync(0xffffffffu, l1 > thr);
        uint64_t cmask = ((uint64_t)mhi << 32) | (uint64_t)mlo;

        const float4* xr = (const float4*)(X + (size_t)i * D_DIM);

        float v1e = -3.4e38f, v2e = -3.4e38f;
        int i1e = 0, i2e = 0;
        while (cmask) {
            const int c = __ffsll((long long)cmask) - 1;
            cmask &= cmask - 1;
            const float4* wr = (const float4*)(W + (size_t)c * D_DIM);
            float a0 = 0.f, a1 = 0.f, a2 = 0.f, a3 = 0.f;
#pragma unroll
            for (int j = 0; j < 32; ++j) {
                const float4 xa = xr[j * 32 + lane];
                const float4 wa = wr[j * 32 + lane];
                a0 = fmaf(xa.x, wa.x, a0);
                a1 = fmaf(xa.y, wa.y, a1);
                a2 = fmaf(xa.z, wa.z, a2);
                a3 = fmaf(xa.w, wa.w, a3);
            }
            float tot = ((a0 + a1) + a2) + a3;
#pragma unroll
            for (int off = 16; off; off >>= 1)
                tot += __shfl_xor_sync(0xffffffffu, tot, off);
            if (tot > v1e)      { v2e = v1e; i2e = i1e; v1e = tot; i1e = c; }
            else if (tot > v2e) { v2e = tot; i2e = c; }
        }

        if (lane == 0) {
            const float t = expf(v2e - v1e);
            const float g1n = 1.0f / (1.0f + t);
            const float g2n = t / (1.0f + t);
            const float rnd = jax_uniform_partitionable((uint32_t)i);
            const int w2 = (rnd < 2.0f * g2n) ? 1 : 0;

            const int blkb = i >> 7;
            const int oe1 = g_e1[i], oe2 = g_e2[i], ow2 = g_want2[i];
            if (i1e != oe1) {
                atomicSub(&g_bc1T[oe1 * 128 + blkb], 1);
                atomicAdd(&g_bc1T[i1e * 128 + blkb], 1);
            }
            if (ow2) atomicSub(&g_bc2T[oe2 * 128 + blkb], 1);
            if (w2)  atomicAdd(&g_bc2T[i2e * 128 + blkb], 1);

            g_e1[i] = i1e;
            g_e2[i] = i2e;
            g_g1n[i] = g1n;
            g_g2n[i] = g2n;
            g_want2[i] = w2;
        }
    }
}

// ---------------- final ranks + full-row write; per-block inline prefix scan ----------------
__global__ __launch_bounds__(128)
void assign_kernel(float* __restrict__ out) {
    __shared__ int wc1[4][64];
    __shared__ int wc2[4][64];
    __shared__ int base1s[64], base2s[64], cap2s[64];
    const int t = threadIdx.x, warp = t >> 5, lane = t & 31;
    const int blk = blockIdx.x;

    ((int*)wc1)[t] = 0; ((int*)wc1)[t + 128] = 0;
    ((int*)wc2)[t] = 0; ((int*)wc2)[t + 128] = 0;

    // inline scan: threads 0..63 -> bc1 prefix + totals (cap2); 64..127 -> bc2 prefix
    if (t < 64) {
        const int4* p = (const int4*)(g_bc1T + t * 128);
        int tot = 0, pre = 0;
#pragma unroll
        for (int q = 0; q < 32; ++q) {
            const int4 v = p[q];
            const int i0 = q * 4;
            tot += ((v.x + v.y) + v.z) + v.w;
            pre += (i0 < blk ? v.x : 0) + (i0 + 1 < blk ? v.y : 0) +
                   (i0 + 2 < blk ? v.z : 0) + (i0 + 3 < blk ? v.w : 0);
        }
        base1s[t] = pre;
        cap2s[t] = CAP - (tot < CAP ? tot : CAP);
    } else {
        const int e = t - 64;
        const int4* p = (const int4*)(g_bc2T + e * 128);
        int pre = 0;
#pragma unroll
        for (int q = 0; q < 32; ++q) {
            const int4 v = p[q];
            const int i0 = q * 4;
            pre += (i0 < blk ? v.x : 0) + (i0 + 1 < blk ? v.y : 0) +
                   (i0 + 2 < blk ? v.z : 0) + (i0 + 3 < blk ? v.w : 0);
        }
        base2s[e] = pre;
    }
    __syncthreads();

    const int i  = blk * 128 + t;
    const int e1 = g_e1[i], e2 = g_e2[i], want2 = g_want2[i];
    const unsigned lt = (1u << lane) - 1u;

    const unsigned m1 = __match_any_sync(0xffffffffu, e1);
    const int lr1 = __popc(m1 & lt);
    if (lr1 == 0) wc1[warp][e1] = __popc(m1);

    const unsigned act2 = __ballot_sync(0xffffffffu, want2);
    const unsigned m2 = __match_any_sync(0xffffffffu, e2) & act2;
    const int lr2 = __popc(m2 & lt);
    if (want2 && lr2 == 0) wc2[warp][e2] = __popc(m2);
    __syncthreads();

    int off1 = 0, off2 = 0;
    for (int w = 0; w < warp; ++w) {
        off1 += wc1[w][e1];
        off2 += wc2[w][e2];
    }

    const int pos1 = base1s[e1] + off1 + lr1 + 1;
    const int pos2 = base2s[e2] + off2 + lr2 + 1;
    const float val1 = (pos1 <= CAP) ? g_g1n[i] : 0.f;
    const float val2 = (want2 && pos2 <= cap2s[e2]) ? g_g2n[i] : 0.f;

    float4* op = (float4*)(out + (size_t)i * 64);
#pragma unroll
    for (int q = 0; q < 16; ++q) {
        float4 z = make_float4(0.f, 0.f, 0.f, 0.f);
        if ((e1 >> 2) == q) ((float*)&z)[e1 & 3] = val1;
        if ((e2 >> 2) == q) ((float*)&z)[e2 & 3] = val2;
        op[q] = z;
    }
}

// ---------------- launcher ----------------
extern "C" void kernel_launch(void* const* d_in, const int* in_sizes, int n_in,
                              void* d_out, int out_size) {
    const float* x = (const float*)d_in[0];
    const float* w = (const float*)d_in[1];
    float* out = (float*)d_out;

    cudaFuncSetAttribute(gemm_fused, cudaFuncAttributeMaxDynamicSharedMemorySize, GEMM_SMEM);

    wconv_kernel<<<512, 256>>>(w);
    gemm_fused<<<S_TOK / BM, 512, GEMM_SMEM>>>(x);
    rescue_exact<<<128, 256>>>(x, w);
    assign_kernel<<<S_TOK / 128, 128>>>(out);
}